// round 14
// baseline (speedup 1.0000x reference)
#include <cuda_runtime.h>
#include <math.h>
#include <stdint.h>
#include <cuda_bf16.h>

// ---------------- problem constants ----------------
static const int NN   = 50000;   // nodes
static const int EE   = 400000;  // edges
static const int FIN  = 64;
static const int EIN  = 16;
static const int HH   = 128;
static const int LL   = 4;
static const int GG   = 256;
static const int OUTC = 12;

// ---------------- scratch (static device globals; no runtime alloc) ----------------
__device__ float d_eap[(size_t)EE * EIN];       // permuted raw edge attrs (CSR order)
__device__ float d_cmb[(size_t)NN * 3 * HH];    // [hd+tl | hs | z+b2] per node
__device__ __nv_bfloat16 d_agh[(size_t)NN * 4 * HH];
__device__ __nv_bfloat16 d_agl[(size_t)NN * 4 * HH];
__device__ float d_y  [(size_t)NN * 3 * HH];    // agg @ Qcat
__device__ __nv_bfloat16 d_hh0[(size_t)NN * HH];
__device__ __nv_bfloat16 d_hl0[(size_t)NN * HH];
__device__ __nv_bfloat16 d_hh1[(size_t)NN * HH];
__device__ __nv_bfloat16 d_hl1[(size_t)NN * HH];
__device__ int   d_deg [NN];
__device__ int   d_offs[NN + 1];
__device__ int   d_cnt [NN];
__device__ int   d_srcp[EE];
__device__ float d_amp[NN];
__device__ float d_att[NN];
__device__ float d_avg[1];
__device__ float d_S   [LL * EIN * HH];         // eW@Wenc@Wpre2 per layer [16,128]
__device__ float d_T1  [LL * EIN * HH];         // temp (batched)
__device__ float d_uv  [LL * HH];               // temp (batched)
__device__ float d_Y   [(size_t)LL * 13 * HH * HH]; // [P0|P1..P12]@lin per layer [1664,128]
__device__ float d_cbias[LL * 3 * HH];          // [tl | 0 | b2] per layer
__device__ float d_g   [GG * HH];
// transposed bf16-split weights (Bt layout: [N,K] row-major)
__device__ __nv_bfloat16 d_Wch[LL * 3 * HH * HH], d_Wcl[LL * 3 * HH * HH];   // [384,128]: W0|W1|Q0
__device__ __nv_bfloat16 d_Qch[LL * 3 * HH * 4 * HH], d_Qcl[LL * 3 * HH * 4 * HH]; // [384,512]

// ================= common MMA helpers =================
static const int HPAD = 40;                 // padded K-stride in bf16 (conflict-free ldmatrix)

#define LDSM4(R, ADDR) \
    asm volatile("ldmatrix.sync.aligned.m8n8.x4.shared.b16 {%0,%1,%2,%3}, [%4];" \
        : "=r"((R)[0]), "=r"((R)[1]), "=r"((R)[2]), "=r"((R)[3]) : "r"(ADDR))

#define MMA16816(D, A, B) \
    asm volatile("mma.sync.aligned.m16n8k16.row.col.f32.bf16.bf16.f32 " \
        "{%0,%1,%2,%3}, {%4,%5,%6,%7}, {%8,%9}, {%0,%1,%2,%3};" \
        : "+f"((D)[0]), "+f"((D)[1]), "+f"((D)[2]), "+f"((D)[3]) \
        : "r"((A)[0]), "r"((A)[1]), "r"((A)[2]), "r"((A)[3]), "r"((B)[0]), "r"((B)[1]))

__device__ __forceinline__ uint32_t smem_u32(const void* p) {
    uint32_t a;
    asm("{ .reg .u64 t; cvta.to.shared.u64 t, %1; cvt.u32.u64 %0, t; }" : "=r"(a) : "l"(p));
    return a;
}

__device__ __forceinline__ void split1(float x, __nv_bfloat16& h, __nv_bfloat16& l) {
    h = __float2bfloat16(x);
    l = __float2bfloat16(x - __bfloat162float(h));
}

// ================= bf16x3 GEMM (mma.sync, 128x128 tile, 2 CTA/SM) =================
// Single barrier per K-chunk: wait -> barrier -> compute(ks=0) -> issue(ch+1) -> compute(ks=1).
static const int TILEB = 128 * HPAD * 2;    // 10240 B per tile
static const int BUFB  = 4 * TILEB;         // Ah,Al,Bh,Bl
static const int TSMEM = 2 * BUFB;          // 81920 B

__global__ void __launch_bounds__(256, 2) hmma_kernel(
    const __nv_bfloat16* __restrict__ Ah, const __nv_bfloat16* __restrict__ Al,
    const __nv_bfloat16* __restrict__ Bh, const __nv_bfloat16* __restrict__ Bl,
    float* __restrict__ C, int ldc, int M, int K,
    const float* __restrict__ bias)
{
    extern __shared__ char smem[];
    const uint32_t sb = smem_u32(smem);
    const int tid = threadIdx.x, lane = tid & 31, wid = tid >> 5;
    const int warp_m = wid & 3, warp_n = wid >> 2;         // 4 x 2 warps
    const int m0 = blockIdx.x * 128, n0 = blockIdx.y * 128;

    const int OAH = 0, OAL = TILEB, OBH = 2 * TILEB, OBL = 3 * TILEB;

    float acc[2][8][4];
#pragma unroll
    for (int i = 0; i < 2; i++)
#pragma unroll
        for (int j = 0; j < 8; j++)
#pragma unroll
            for (int k = 0; k < 4; k++) acc[i][j][k] = 0.f;

    const int ldr = tid >> 2;
    const int ldc8 = (tid & 3) * 8;
    auto issue_chunk = [&](int buf, int k0) {
        uint32_t bo = sb + buf * BUFB;
#pragma unroll
        for (int half = 0; half < 2; half++) {
            int r = half * 64 + ldr;
            uint32_t soff = (uint32_t)(r * HPAD + ldc8) * 2;
            int arow = m0 + r;
            int asz = (arow < M) ? 16 : 0;
            const void* gah = Ah + (size_t)arow * K + k0 + ldc8;
            const void* gal = Al + (size_t)arow * K + k0 + ldc8;
            asm volatile("cp.async.cg.shared.global [%0], [%1], 16, %2;"
                         :: "r"(bo + OAH + soff), "l"(gah), "r"(asz));
            asm volatile("cp.async.cg.shared.global [%0], [%1], 16, %2;"
                         :: "r"(bo + OAL + soff), "l"(gal), "r"(asz));
            const void* gbh = Bh + (size_t)(n0 + r) * K + k0 + ldc8;
            const void* gbl = Bl + (size_t)(n0 + r) * K + k0 + ldc8;
            asm volatile("cp.async.cg.shared.global [%0], [%1], 16;"
                         :: "r"(bo + OBH + soff), "l"(gbh));
            asm volatile("cp.async.cg.shared.global [%0], [%1], 16;"
                         :: "r"(bo + OBL + soff), "l"(gbl));
        }
        asm volatile("cp.async.commit_group;");
    };

    const int a_r  = lane & 15;
    const int a_kg = (lane >> 4) * 8;
    const int b_r  = (lane & 7) + ((lane >> 4) * 8);
    const int b_kg = ((lane >> 3) & 1) * 8;

    const int nchunks = K >> 5;
    issue_chunk(0, 0);

    for (int ch = 0; ch < nchunks; ch++) {
        asm volatile("cp.async.wait_group 0;");
        __syncthreads();

        uint32_t bo = sb + (ch & 1) * BUFB;
#pragma unroll
        for (int ks = 0; ks < 2; ks++) {
            int kc = ks * 16;
            uint32_t afh[2][4], afl[2][4];
#pragma unroll
            for (int mt = 0; mt < 2; mt++) {
                int row = warp_m * 32 + mt * 16 + a_r;
                uint32_t ad = bo + (uint32_t)(row * HPAD + kc + a_kg) * 2;
                LDSM4(afh[mt], ad + OAH);
                LDSM4(afl[mt], ad + OAL);
            }
#pragma unroll
            for (int np = 0; np < 4; np++) {
                uint32_t bfh[4], bfl[4];
                int nrow = warp_n * 64 + np * 16 + b_r;
                uint32_t bd = bo + (uint32_t)(nrow * HPAD + kc + b_kg) * 2;
                LDSM4(bfh, bd + OBH);
                LDSM4(bfl, bd + OBL);
#pragma unroll
                for (int mt = 0; mt < 2; mt++) {
                    MMA16816(acc[mt][np * 2 + 0], afh[mt], (&bfh[0]));
                    MMA16816(acc[mt][np * 2 + 1], afh[mt], (&bfh[2]));
                    MMA16816(acc[mt][np * 2 + 0], afl[mt], (&bfh[0]));
                    MMA16816(acc[mt][np * 2 + 1], afl[mt], (&bfh[2]));
                    MMA16816(acc[mt][np * 2 + 0], afh[mt], (&bfl[0]));
                    MMA16816(acc[mt][np * 2 + 1], afh[mt], (&bfl[2]));
                }
            }
            if (ks == 0 && ch + 1 < nchunks) issue_chunk((ch + 1) & 1, (ch + 1) << 5);
        }
    }

    const int mrow = m0 + warp_m * 32;
    const int ncol = n0 + warp_n * 64;
#pragma unroll
    for (int mt = 0; mt < 2; mt++) {
#pragma unroll
        for (int nt = 0; nt < 8; nt++) {
            int c = ncol + nt * 8 + (lane & 3) * 2;
            float2 bv = bias ? *(const float2*)&bias[c] : make_float2(0.f, 0.f);
            int r0 = mrow + mt * 16 + (lane >> 2);
            if (r0 < M) {
                float2 v = make_float2(acc[mt][nt][0] + bv.x, acc[mt][nt][1] + bv.y);
                *(float2*)&C[(size_t)r0 * ldc + c] = v;
            }
            int r1 = r0 + 8;
            if (r1 < M) {
                float2 v = make_float2(acc[mt][nt][2] + bv.x, acc[mt][nt][3] + bv.y);
                *(float2*)&C[(size_t)r1 * ldc + c] = v;
            }
        }
    }
}

// ---------------- fp32 SGEMM (batched fp32-out / split-out) ----------------
template <int MODE>   // 0 = fp32 C, 1 = bf16 hi/lo split output
__device__ __forceinline__ void sgemm_body(
    const float* A, int lda, const float* B, int ldb, float* C, int ldc,
    int M, int N, int K, const float* bias,
    __nv_bfloat16* Hi, __nv_bfloat16* Lo)
{
    const int BM = 128, BN = 128, BK = 8;
    __shared__ float As[BK][BM];
    __shared__ float Bs[BK][BN];
    int tid = threadIdx.x;
    int brow = blockIdx.y, bcol = blockIdx.x;
    int aRow = tid >> 1, aCol4 = (tid & 1) * 4;
    int bRow = tid >> 5, bCol4 = (tid & 31) * 4;
    int tr = (tid >> 4) * 8, tc = (tid & 15) * 8;
    float acc[8][8];
#pragma unroll
    for (int i = 0; i < 8; i++)
#pragma unroll
        for (int j = 0; j < 8; j++) acc[i][j] = 0.f;
    int gArow = brow * BM + aRow;
    bool aValid = gArow < M;
    const float* Aptr = A + (long)(aValid ? gArow : 0) * lda + aCol4;
    const float* Bptr = B + (long)bRow * ldb + (long)bcol * BN + bCol4;
    for (int k0 = 0; k0 < K; k0 += BK) {
        float4 av = aValid ? *(const float4*)(Aptr + k0) : make_float4(0.f, 0.f, 0.f, 0.f);
        float4 bv = *(const float4*)(Bptr + (long)k0 * ldb);
        As[aCol4 + 0][aRow] = av.x; As[aCol4 + 1][aRow] = av.y;
        As[aCol4 + 2][aRow] = av.z; As[aCol4 + 3][aRow] = av.w;
        *(float4*)&Bs[bRow][bCol4] = bv;
        __syncthreads();
#pragma unroll
        for (int kk = 0; kk < BK; kk++) {
            float ar[8], br[8];
#pragma unroll
            for (int i = 0; i < 8; i++) ar[i] = As[kk][tr + i];
#pragma unroll
            for (int j = 0; j < 8; j++) br[j] = Bs[kk][tc + j];
#pragma unroll
            for (int i = 0; i < 8; i++)
#pragma unroll
                for (int j = 0; j < 8; j++)
                    acc[i][j] = fmaf(ar[i], br[j], acc[i][j]);
        }
        __syncthreads();
    }
#pragma unroll
    for (int i = 0; i < 8; i++) {
        int row = brow * BM + tr + i;
        if (row < M) {
#pragma unroll
            for (int j = 0; j < 8; j += 4) {
                int col = bcol * BN + tc + j;
                float4 v;
                v.x = acc[i][j + 0] + (bias ? bias[col + 0] : 0.f);
                v.y = acc[i][j + 1] + (bias ? bias[col + 1] : 0.f);
                v.z = acc[i][j + 2] + (bias ? bias[col + 2] : 0.f);
                v.w = acc[i][j + 3] + (bias ? bias[col + 3] : 0.f);
                if (MODE == 0) {
                    *(float4*)&C[(long)row * ldc + col] = v;
                } else {
                    __nv_bfloat16 h0, l0, h1, l1, h2, l2, h3, l3;
                    split1(v.x, h0, l0); split1(v.y, h1, l1);
                    split1(v.z, h2, l2); split1(v.w, h3, l3);
                    __nv_bfloat162 hp0; hp0.x = h0; hp0.y = h1;
                    __nv_bfloat162 hp1; hp1.x = h2; hp1.y = h3;
                    __nv_bfloat162 lp0; lp0.x = l0; lp0.y = l1;
                    __nv_bfloat162 lp1; lp1.x = l2; lp1.y = l3;
                    long o = (long)row * ldc + col;
                    *(__nv_bfloat162*)&Hi[o]     = hp0;
                    *(__nv_bfloat162*)&Hi[o + 2] = hp1;
                    *(__nv_bfloat162*)&Lo[o]     = lp0;
                    *(__nv_bfloat162*)&Lo[o + 2] = lp1;
                }
            }
        }
    }
}

__global__ void __launch_bounds__(256) sgemm_split_kernel(
    const float* __restrict__ A, int lda,
    const float* __restrict__ B, int ldb,
    int M, int N, int K, const float* __restrict__ bias,
    __nv_bfloat16* __restrict__ Hi, __nv_bfloat16* __restrict__ Lo)
{
    sgemm_body<1>(A, lda, B, ldb, nullptr, N, M, N, K, bias, Hi, Lo);
}

__global__ void __launch_bounds__(256) sgemm_batched_kernel(
    const float* __restrict__ A, int lda, long strideA,
    const float* __restrict__ B, int ldb, long strideB,
    float* __restrict__ C, int ldc, long strideC,
    int M, int N, int K)
{
    int l = blockIdx.z;
    sgemm_body<0>(A + (long)l * strideA, lda, B + (long)l * strideB, ldb,
                  C + (long)l * strideC, ldc, M, N, K, nullptr, nullptr, nullptr);
}

// ---------------- small helper kernels ----------------
__global__ void count_kernel(const int* __restrict__ dst, int n) {
    int i = blockIdx.x * blockDim.x + threadIdx.x;
    if (i < n) atomicAdd(&d_deg[dst[i]], 1);
}

__global__ void scan_kernel() {
    __shared__ int sh[1024];
    __shared__ int carry;
    if (threadIdx.x == 0) carry = 0;
    __syncthreads();
    for (int base = 0; base < NN; base += 1024) {
        int i = base + (int)threadIdx.x;
        int v = (i < NN) ? d_deg[i] : 0;
        sh[threadIdx.x] = v;
        __syncthreads();
        for (int off = 1; off < 1024; off <<= 1) {
            int t = (threadIdx.x >= (unsigned)off) ? sh[threadIdx.x - off] : 0;
            __syncthreads();
            sh[threadIdx.x] += t;
            __syncthreads();
        }
        if (i < NN) d_offs[i] = carry + sh[threadIdx.x] - v;
        __syncthreads();
        if (threadIdx.x == 1023) carry += sh[1023];
        __syncthreads();
    }
    if (threadIdx.x == 0) d_offs[NN] = carry;
}

// scatter CSR: srcp + permuted eattr rows in one pass
__global__ void scatter_kernel(const int* __restrict__ src, const int* __restrict__ dst,
                               const float* __restrict__ ea, int n) {
    int i = blockIdx.x * blockDim.x + threadIdx.x;
    if (i < n) {
        int pos = atomicAdd(&d_cnt[dst[i]], 1);
        d_srcp[pos] = src[i];
        const float4* s = (const float4*)(ea + (size_t)i * EIN);
        float4* d = (float4*)(d_eap + (size_t)pos * EIN);
        d[0] = s[0]; d[1] = s[1]; d[2] = s[2]; d[3] = s[3];
    }
}

__global__ void logdeg_sum_kernel() {
    __shared__ float sh[256];
    float s = 0.f;
    for (int i = blockIdx.x * blockDim.x + threadIdx.x; i < NN; i += gridDim.x * blockDim.x)
        s += log1pf((float)d_deg[i]);
    sh[threadIdx.x] = s;
    __syncthreads();
    for (int off = 128; off > 0; off >>= 1) {
        if (threadIdx.x < (unsigned)off) sh[threadIdx.x] += sh[threadIdx.x + off];
        __syncthreads();
    }
    if (threadIdx.x == 0) atomicAdd(&d_avg[0], sh[0]);
}

__global__ void scalers_kernel() {
    int i = blockIdx.x * blockDim.x + threadIdx.x;
    if (i < NN) {
        float avg  = d_avg[0] / (float)NN;
        float degc = fmaxf((float)d_deg[i], 1.f);
        float l    = logf(degc + 1.f);
        d_amp[i] = l / avg;
        d_att[i] = avg / l;
    }
}

// batched vecmat over blockIdx.x = layer; writes into arbitrary strided output
__global__ void vecmatb_kernel(const float* __restrict__ v, long sv,
                               const float* __restrict__ W, int ldw, long sw,
                               const float* __restrict__ badd, long sb,
                               float* __restrict__ out, long so) {
    int l = blockIdx.x, c = threadIdx.x;
    const float* vl = v + l * sv;
    const float* Wl = W + l * sw;
    float s = 0.f;
    for (int j = 0; j < HH; j++) s = fmaf(vl[j], Wl[j * ldw + c], s);
    out[l * so + c] = s + badd[l * sb + c];
}

// Wc [384,128] from preW (W0,W1) and Y rows 0..127 (Q0); batched over z
__global__ void wconv_kernel(const float* __restrict__ preW) {
    int l = blockIdx.z;
    int i = blockIdx.x * blockDim.x + threadIdx.x;   // 384*128
    if (i >= 384 * 128) return;
    int n = i >> 7, k = i & 127;
    float v;
    if (n < 256) {
        int c = n & 127;
        v = preW[(size_t)l * 3 * HH * HH + ((n >> 7) ? HH * HH : 0) + k * HH + c];
    } else {
        v = d_Y[(size_t)l * 13 * HH * HH + (size_t)k * HH + (n - 256)];
    }
    __nv_bfloat16 h, lo; split1(v, h, lo);
    size_t o = (size_t)l * 3 * HH * HH + (size_t)n * HH + k;
    d_Wch[o] = h; d_Wcl[o] = lo;
}

// Qc [384,512] from Y rows 128..1663; batched over z
__global__ void qconv_kernel() {
    int l = blockIdx.z;
    int i = blockIdx.x * blockDim.x + threadIdx.x;   // 384*512
    if (i >= 384 * 512) return;
    int n = i >> 9, k = i & 511;
    int q = n >> 7, c = n & 127;
    float v = d_Y[(size_t)l * 13 * HH * HH + (size_t)(128 + q * 512 + k) * HH + c];
    __nv_bfloat16 h, lo; split1(v, h, lo);
    size_t o = (size_t)l * 384 * 512 + (size_t)n * 512 + k;
    d_Qch[o] = h; d_Qcl[o] = lo;
}

// per-edge message value for column c (16 FMAs against S registers)
__device__ __forceinline__ float edge_msg(int r, const float* Sreg, float base) {
    const float4* ea = (const float4*)(d_eap + (size_t)r * EIN);
    float4 e0 = ea[0], e1 = ea[1], e2 = ea[2], e3 = ea[3];
    float v = base;
    v = fmaf(e0.x, Sreg[0],  v); v = fmaf(e0.y, Sreg[1],  v);
    v = fmaf(e0.z, Sreg[2],  v); v = fmaf(e0.w, Sreg[3],  v);
    v = fmaf(e1.x, Sreg[4],  v); v = fmaf(e1.y, Sreg[5],  v);
    v = fmaf(e1.z, Sreg[6],  v); v = fmaf(e1.w, Sreg[7],  v);
    v = fmaf(e2.x, Sreg[8],  v); v = fmaf(e2.y, Sreg[9],  v);
    v = fmaf(e2.z, Sreg[10], v); v = fmaf(e2.w, Sreg[11], v);
    v = fmaf(e3.x, Sreg[12], v); v = fmaf(e3.y, Sreg[13], v);
    v = fmaf(e3.z, Sreg[14], v); v = fmaf(e3.w, Sreg[15], v);
    return v;
}

// segmented aggregation, grid-stride over nodes; 4-edge unroll for gather MLP
// (single isolated change vs R13 — deconfounds R11).
__global__ void __launch_bounds__(128) agg_kernel(const float* __restrict__ S) {
    int c = threadIdx.x;
    float Sreg[16];
#pragma unroll
    for (int k = 0; k < 16; k++) Sreg[k] = S[k * HH + c];
    for (int node = blockIdx.x; node < NN; node += gridDim.x) {
        int s = d_offs[node], e = d_offs[node + 1];
        float hd = d_cmb[(size_t)node * 384 + c];
        float sum = 0.f, ss = 0.f, mn = INFINITY, mx = -INFINITY;
        int r = s;
        for (; r + 4 <= e; r += 4) {
            int sp0 = d_srcp[r],     sp1 = d_srcp[r + 1];
            int sp2 = d_srcp[r + 2], sp3 = d_srcp[r + 3];
            float hs0 = d_cmb[(size_t)sp0 * 384 + 128 + c];
            float hs1 = d_cmb[(size_t)sp1 * 384 + 128 + c];
            float hs2 = d_cmb[(size_t)sp2 * 384 + 128 + c];
            float hs3 = d_cmb[(size_t)sp3 * 384 + 128 + c];
            float v0 = edge_msg(r,     Sreg, hd + hs0);
            float v1 = edge_msg(r + 1, Sreg, hd + hs1);
            float v2 = edge_msg(r + 2, Sreg, hd + hs2);
            float v3 = edge_msg(r + 3, Sreg, hd + hs3);
            sum += v0; ss = fmaf(v0, v0, ss); mn = fminf(mn, v0); mx = fmaxf(mx, v0);
            sum += v1; ss = fmaf(v1, v1, ss); mn = fminf(mn, v1); mx = fmaxf(mx, v1);
            sum += v2; ss = fmaf(v2, v2, ss); mn = fminf(mn, v2); mx = fmaxf(mx, v2);
            sum += v3; ss = fmaf(v3, v3, ss); mn = fminf(mn, v3); mx = fmaxf(mx, v3);
        }
        for (; r + 2 <= e; r += 2) {
            int sp0 = d_srcp[r], sp1 = d_srcp[r + 1];
            float hs0 = d_cmb[(size_t)sp0 * 384 + 128 + c];
            float hs1 = d_cmb[(size_t)sp1 * 384 + 128 + c];
            float v0 = edge_msg(r,     Sreg, hd + hs0);
            float v1 = edge_msg(r + 1, Sreg, hd + hs1);
            sum += v0; ss = fmaf(v0, v0, ss); mn = fminf(mn, v0); mx = fmaxf(mx, v0);
            sum += v1; ss = fmaf(v1, v1, ss); mn = fminf(mn, v1); mx = fmaxf(mx, v1);
        }
        if (r < e) {
            int sp = d_srcp[r];
            float v = edge_msg(r, Sreg, hd + d_cmb[(size_t)sp * 384 + 128 + c]);
            sum += v; ss = fmaf(v, v, ss);
            mn = fminf(mn, v); mx = fmaxf(mx, v);
        }
        float deg  = (float)(e - s);
        float degc = fmaxf(deg, 1.f);
        float mean = sum / degc;
        float var  = ss / degc - mean * mean;
        float sd   = sqrtf(fmaxf(var, 0.f) + 1e-5f);
        if (e == s) { mn = 0.f; mx = 0.f; }
        size_t o = (size_t)node * 512;
        __nv_bfloat16 h, l;
        split1(mean, h, l); d_agh[o +       c] = h; d_agl[o +       c] = l;
        split1(mn,   h, l); d_agh[o + 128 + c] = h; d_agl[o + 128 + c] = l;
        split1(mx,   h, l); d_agh[o + 256 + c] = h; d_agl[o + 256 + c] = l;
        split1(sd,   h, l); d_agh[o + 384 + c] = h; d_agl[o + 384 + c] = l;
    }
}

// h_next = relu(z(+b2) + y0 + amp*y1 + att*y2); writes bf16 splits only
__global__ void combine_kernel(__nv_bfloat16* __restrict__ hh, __nv_bfloat16* __restrict__ hl) {
    int i = blockIdx.x * blockDim.x + threadIdx.x;   // NN*32 threads, 4 cols each
    if (i >= NN * 32) return;
    int node = i >> 5, c = (i & 31) * 4;
    size_t co = (size_t)node * 384;
    float4 zv = *(const float4*)&d_cmb[co + 256 + c];
    float4 y0 = *(const float4*)&d_y[co + c];
    float4 y1 = *(const float4*)&d_y[co + 128 + c];
    float4 y2 = *(const float4*)&d_y[co + 256 + c];
    float amp = d_amp[node], att = d_att[node];
    float v0 = fmaxf(zv.x + y0.x + amp * y1.x + att * y2.x, 0.f);
    float v1 = fmaxf(zv.y + y0.y + amp * y1.y + att * y2.y, 0.f);
    float v2 = fmaxf(zv.z + y0.z + amp * y1.z + att * y2.z, 0.f);
    float v3 = fmaxf(zv.w + y0.w + amp * y1.w + att * y2.w, 0.f);
    __nv_bfloat16 h0, l0, h1, l1, h2, l2, h3, l3;
    split1(v0, h0, l0); split1(v1, h1, l1); split1(v2, h2, l2); split1(v3, h3, l3);
    __nv_bfloat162 hp0; hp0.x = h0; hp0.y = h1;
    __nv_bfloat162 hp1; hp1.x = h2; hp1.y = h3;
    __nv_bfloat162 lp0; lp0.x = l0; lp0.y = l1;
    __nv_bfloat162 lp1; lp1.x = l2; lp1.y = l3;
    size_t o = (size_t)node * HH + c;
    *(__nv_bfloat162*)&hh[o]     = hp0;
    *(__nv_bfloat162*)&hh[o + 2] = hp1;
    *(__nv_bfloat162*)&hl[o]     = lp0;
    *(__nv_bfloat162*)&hl[o + 2] = lp1;
}

// pool from bf16 splits (h = hi + lo)
__global__ void pool_kernel(const __nv_bfloat16* __restrict__ hh,
                            const __nv_bfloat16* __restrict__ hl,
                            const int* __restrict__ batch) {
    int i = blockIdx.x * blockDim.x + threadIdx.x;
    if (i >= NN * HH) return;
    int node = i >> 7, c = i & 127;
    float h = __bfloat162float(hh[i]) + __bfloat162float(hl[i]);
    atomicAdd(&d_g[batch[node] * HH + c], h);
}

__global__ void head_kernel(const float* __restrict__ W, const float* __restrict__ b,
                            float* __restrict__ out) {
    __shared__ float sh[HH];
    sh[threadIdx.x] = d_g[blockIdx.x * HH + threadIdx.x];
    __syncthreads();
    if (threadIdx.x < OUTC) {
        float s = b[threadIdx.x];
        for (int k = 0; k < HH; k++) s = fmaf(sh[k], W[k * OUTC + threadIdx.x], s);
        out[blockIdx.x * OUTC + threadIdx.x] = s;
    }
}

// ---------------- host orchestration ----------------
static void gemm_b(const float* A, int lda, long sA, const float* B, int ldb, long sB,
                   float* C, int ldc, long sC, int M, int N, int K) {
    dim3 grid(N / 128, (M + 127) / 128, LL);
    sgemm_batched_kernel<<<grid, 256>>>(A, lda, sA, B, ldb, sB, C, ldc, sC, M, N, K);
}

static void tgemm(const __nv_bfloat16* Ah, const __nv_bfloat16* Al,
                  const __nv_bfloat16* Bh, const __nv_bfloat16* Bl,
                  float* C, int ldc, int M, int N, int K, const float* bias) {
    dim3 grid((M + 127) / 128, N / 128);
    hmma_kernel<<<grid, 256, TSMEM>>>(Ah, Al, Bh, Bl, C, ldc, M, K, bias);
}

template <typename T>
static T* sym(const void* symbol) {
    void* p = nullptr;
    cudaGetSymbolAddress(&p, symbol);
    return (T*)p;
}

extern "C" void kernel_launch(void* const* d_in, const int* in_sizes, int n_in,
                              void* d_out, int out_size) {
    const float* x     = (const float*)d_in[0];
    const float* eattr = (const float*)d_in[1];
    const int*   src   = (const int*)  d_in[2];
    const int*   dst   = (const int*)  d_in[3];
    const int*   batch = (const int*)  d_in[4];
    const float* nW    = (const float*)d_in[5];
    const float* nb    = (const float*)d_in[6];
    const float* eW    = (const float*)d_in[7];
    const float* eb    = (const float*)d_in[8];
    const float* encW  = (const float*)d_in[9];
    const float* encb  = (const float*)d_in[10];
    const float* preW  = (const float*)d_in[11];
    const float* preb  = (const float*)d_in[12];
    const float* postW = (const float*)d_in[13];
    const float* postb = (const float*)d_in[14];
    const float* linW  = (const float*)d_in[15];
    const float* linb  = (const float*)d_in[16];
    const float* headW = (const float*)d_in[17];
    const float* headb = (const float*)d_in[18];
    float* out = (float*)d_out;

    float* cmb  = sym<float>(d_cmb);
    __nv_bfloat16* agh = sym<__nv_bfloat16>(d_agh);
    __nv_bfloat16* agl = sym<__nv_bfloat16>(d_agl);
    float* y    = sym<float>(d_y);
    __nv_bfloat16* hh[2] = { sym<__nv_bfloat16>(d_hh0), sym<__nv_bfloat16>(d_hh1) };
    __nv_bfloat16* hl[2] = { sym<__nv_bfloat16>(d_hl0), sym<__nv_bfloat16>(d_hl1) };
    int*   deg  = sym<int>(d_deg);
    int*   offs = sym<int>(d_offs);
    int*   cnt  = sym<int>(d_cnt);
    float* avg  = sym<float>(d_avg);
    float* S    = sym<float>(d_S);
    float* T1   = sym<float>(d_T1);
    float* uv   = sym<float>(d_uv);
    float* Yb   = sym<float>(d_Y);
    float* cbias= sym<float>(d_cbias);
    float* g    = sym<float>(d_g);
    __nv_bfloat16* Wch = sym<__nv_bfloat16>(d_Wch); __nv_bfloat16* Wcl = sym<__nv_bfloat16>(d_Wcl);
    __nv_bfloat16* Qch = sym<__nv_bfloat16>(d_Qch); __nv_bfloat16* Qcl = sym<__nv_bfloat16>(d_Qcl);

    cudaFuncSetAttribute(hmma_kernel, cudaFuncAttributeMaxDynamicSharedMemorySize, TSMEM);

    const int TPB = 256;

    // ---- graph structure ----
    cudaMemsetAsync(deg, 0, NN * sizeof(int), 0);
    cudaMemsetAsync(avg, 0, sizeof(float), 0);
    cudaMemsetAsync(cbias, 0, LL * 3 * HH * sizeof(float), 0);
    count_kernel<<<(EE + TPB - 1) / TPB, TPB>>>(dst, EE);
    scan_kernel<<<1, 1024>>>();
    cudaMemcpyAsync(cnt, offs, NN * sizeof(int), cudaMemcpyDeviceToDevice, 0);
    scatter_kernel<<<(EE + TPB - 1) / TPB, TPB>>>(src, dst, eattr, EE);
    logdeg_sum_kernel<<<256, 256>>>();
    scalers_kernel<<<(NN + TPB - 1) / TPB, TPB>>>();

    // ---- node embedding: GEMM straight into bf16 splits ----
    {
        dim3 grid(HH / 128, (NN + 127) / 128);
        sgemm_split_kernel<<<grid, 256>>>(x, FIN, nW, HH, NN, HH, FIN, nb, hh[0], hl[0]);
    }

    // ---- batched per-layer weight precompute ----
    gemm_b(eW, HH, 0, encW, HH, (long)HH * HH, T1, HH, (long)EIN * HH, EIN, HH, HH);
    gemm_b(T1, HH, (long)EIN * HH, preW + 2 * HH * HH, HH, (long)3 * HH * HH,
           S, HH, (long)EIN * HH, EIN, HH, HH);
    gemm_b(postW, HH, (long)13 * HH * HH, linW, HH, (long)HH * HH,
           Yb, HH, (long)13 * HH * HH, 13 * HH, HH, HH);
    vecmatb_kernel<<<LL, HH>>>(eb, 0, encW, HH, (long)HH * HH, encb, HH, uv, HH);
    vecmatb_kernel<<<LL, HH>>>(uv, HH, preW + 2 * HH * HH, HH, (long)3 * HH * HH,
                               preb, HH, cbias, 3 * HH);
    vecmatb_kernel<<<LL, HH>>>(postb, HH, linW, HH, (long)HH * HH,
                               linb, HH, cbias + 256, 3 * HH);
    {
        dim3 gw((384 * 128 + TPB - 1) / TPB, 1, LL);
        wconv_kernel<<<gw, TPB>>>(preW);
        dim3 gq((384 * 512 + TPB - 1) / TPB, 1, LL);
        qconv_kernel<<<gq, TPB>>>();
    }

    // ---- layers ----
    int cb = 0;
    for (int l = 0; l < LL; l++) {
        // cmb = h @ [W0 | W1 | Q0] + [tl|0|b2]  -> [hd+tl | hs | z+b2], N=384
        tgemm(hh[cb], hl[cb], Wch + (size_t)l * 3 * HH * HH, Wcl + (size_t)l * 3 * HH * HH,
              cmb, 3 * HH, NN, 3 * HH, HH, cbias + l * 3 * HH);
        // segmented aggregation with fused rank-16 edge message -> agg splits [N,512]
        agg_kernel<<<4096, 128>>>(S + (size_t)l * EIN * HH);
        // y = agg @ Qcat_l  [N,384]
        tgemm(agh, agl, Qch + (size_t)l * 384 * 512, Qcl + (size_t)l * 384 * 512,
              y, 3 * HH, NN, 3 * HH, 4 * HH, nullptr);
        // combine -> splits only
        combine_kernel<<<(NN * 32 + TPB - 1) / TPB, TPB>>>(hh[cb ^ 1], hl[cb ^ 1]);
        cb ^= 1;
    }

    // ---- pool + head ----
    cudaMemsetAsync(g, 0, GG * HH * sizeof(float), 0);
    pool_kernel<<<(NN * HH + TPB - 1) / TPB, TPB>>>(hh[cb], hl[cb], batch);
    head_kernel<<<GG, HH>>>(headW, headb, out);
}

// round 15
// speedup vs baseline: 1.0541x; 1.0541x over previous
#include <cuda_runtime.h>
#include <math.h>
#include <stdint.h>
#include <cuda_bf16.h>

// ---------------- problem constants ----------------
static const int NN   = 50000;   // nodes
static const int EE   = 400000;  // edges
static const int FIN  = 64;
static const int EIN  = 16;
static const int HH   = 128;
static const int LL   = 4;
static const int GG   = 256;
static const int OUTC = 12;

// ---------------- scratch (static device globals; no runtime alloc) ----------------
__device__ float d_eap[(size_t)EE * EIN];       // permuted raw edge attrs (CSR order)
__device__ float d_cmb[(size_t)NN * 3 * HH];    // [hd+tl | hs | z+b2] per node
__device__ __nv_bfloat16 d_agh[(size_t)NN * 4 * HH];
__device__ __nv_bfloat16 d_agl[(size_t)NN * 4 * HH];
__device__ float d_y  [(size_t)NN * 3 * HH];    // agg @ Qcat
__device__ __nv_bfloat16 d_hh0[(size_t)NN * HH];
__device__ __nv_bfloat16 d_hl0[(size_t)NN * HH];
__device__ __nv_bfloat16 d_hh1[(size_t)NN * HH];
__device__ __nv_bfloat16 d_hl1[(size_t)NN * HH];
__device__ int   d_deg [NN];
__device__ int   d_offs[NN + 1];
__device__ int   d_cnt [NN];
__device__ int   d_srcp[EE];
__device__ float d_amp[NN];
__device__ float d_att[NN];
__device__ float d_avg[1];
__device__ float d_S   [LL * EIN * HH];         // eW@Wenc@Wpre2 per layer [16,128]
__device__ float d_T1  [LL * EIN * HH];         // temp (batched)
__device__ float d_uv  [LL * HH];               // temp (batched)
__device__ float d_Y   [(size_t)LL * 13 * HH * HH]; // [P0|P1..P12]@lin per layer [1664,128]
__device__ float d_cbias[LL * 3 * HH];          // [tl | 0 | b2] per layer
__device__ float d_g   [GG * HH];
// transposed bf16-split weights (Bt layout: [N,K] row-major)
__device__ __nv_bfloat16 d_Wch[LL * 3 * HH * HH], d_Wcl[LL * 3 * HH * HH];   // [384,128]: W0|W1|Q0
__device__ __nv_bfloat16 d_Qch[LL * 3 * HH * 4 * HH], d_Qcl[LL * 3 * HH * 4 * HH]; // [384,512]

// ================= common MMA helpers =================
static const int HPAD = 40;                 // padded K-stride in bf16 (conflict-free ldmatrix)

#define LDSM4(R, ADDR) \
    asm volatile("ldmatrix.sync.aligned.m8n8.x4.shared.b16 {%0,%1,%2,%3}, [%4];" \
        : "=r"((R)[0]), "=r"((R)[1]), "=r"((R)[2]), "=r"((R)[3]) : "r"(ADDR))

#define MMA16816(D, A, B) \
    asm volatile("mma.sync.aligned.m16n8k16.row.col.f32.bf16.bf16.f32 " \
        "{%0,%1,%2,%3}, {%4,%5,%6,%7}, {%8,%9}, {%0,%1,%2,%3};" \
        : "+f"((D)[0]), "+f"((D)[1]), "+f"((D)[2]), "+f"((D)[3]) \
        : "r"((A)[0]), "r"((A)[1]), "r"((A)[2]), "r"((A)[3]), "r"((B)[0]), "r"((B)[1]))

__device__ __forceinline__ uint32_t smem_u32(const void* p) {
    uint32_t a;
    asm("{ .reg .u64 t; cvta.to.shared.u64 t, %1; cvt.u32.u64 %0, t; }" : "=r"(a) : "l"(p));
    return a;
}

__device__ __forceinline__ void split1(float x, __nv_bfloat16& h, __nv_bfloat16& l) {
    h = __float2bfloat16(x);
    l = __float2bfloat16(x - __bfloat162float(h));
}

// ================= bf16x3 GEMM (mma.sync, 128x128 tile, 2 CTA/SM) =================
// Single barrier per K-chunk: wait -> barrier -> compute(ks=0) -> issue(ch+1) -> compute(ks=1).
// WAR safety: issue(ch+1) writes buf (ch+1)&1; its last readers ran compute(ch-1), and
// barrier(ch)'s release proves all threads finished compute(ch-1).
static const int TILEB = 128 * HPAD * 2;    // 10240 B per tile
static const int BUFB  = 4 * TILEB;         // Ah,Al,Bh,Bl
static const int TSMEM = 2 * BUFB;          // 81920 B

__global__ void __launch_bounds__(256, 2) hmma_kernel(
    const __nv_bfloat16* __restrict__ Ah, const __nv_bfloat16* __restrict__ Al,
    const __nv_bfloat16* __restrict__ Bh, const __nv_bfloat16* __restrict__ Bl,
    float* __restrict__ C, int ldc, int M, int K,
    const float* __restrict__ bias)
{
    extern __shared__ char smem[];
    const uint32_t sb = smem_u32(smem);
    const int tid = threadIdx.x, lane = tid & 31, wid = tid >> 5;
    const int warp_m = wid & 3, warp_n = wid >> 2;         // 4 x 2 warps
    const int m0 = blockIdx.x * 128, n0 = blockIdx.y * 128;

    const int OAH = 0, OAL = TILEB, OBH = 2 * TILEB, OBL = 3 * TILEB;

    float acc[2][8][4];
#pragma unroll
    for (int i = 0; i < 2; i++)
#pragma unroll
        for (int j = 0; j < 8; j++)
#pragma unroll
            for (int k = 0; k < 4; k++) acc[i][j][k] = 0.f;

    const int ldr = tid >> 2;
    const int ldc8 = (tid & 3) * 8;
    auto issue_chunk = [&](int buf, int k0) {
        uint32_t bo = sb + buf * BUFB;
#pragma unroll
        for (int half = 0; half < 2; half++) {
            int r = half * 64 + ldr;
            uint32_t soff = (uint32_t)(r * HPAD + ldc8) * 2;
            int arow = m0 + r;
            int asz = (arow < M) ? 16 : 0;
            const void* gah = Ah + (size_t)arow * K + k0 + ldc8;
            const void* gal = Al + (size_t)arow * K + k0 + ldc8;
            asm volatile("cp.async.cg.shared.global [%0], [%1], 16, %2;"
                         :: "r"(bo + OAH + soff), "l"(gah), "r"(asz));
            asm volatile("cp.async.cg.shared.global [%0], [%1], 16, %2;"
                         :: "r"(bo + OAL + soff), "l"(gal), "r"(asz));
            const void* gbh = Bh + (size_t)(n0 + r) * K + k0 + ldc8;
            const void* gbl = Bl + (size_t)(n0 + r) * K + k0 + ldc8;
            asm volatile("cp.async.cg.shared.global [%0], [%1], 16;"
                         :: "r"(bo + OBH + soff), "l"(gbh));
            asm volatile("cp.async.cg.shared.global [%0], [%1], 16;"
                         :: "r"(bo + OBL + soff), "l"(gbl));
        }
        asm volatile("cp.async.commit_group;");
    };

    const int a_r  = lane & 15;
    const int a_kg = (lane >> 4) * 8;
    const int b_r  = (lane & 7) + ((lane >> 4) * 8);
    const int b_kg = ((lane >> 3) & 1) * 8;

    const int nchunks = K >> 5;
    issue_chunk(0, 0);

    for (int ch = 0; ch < nchunks; ch++) {
        // only group ch is outstanding here (group ch+1 issued mid-compute below)
        asm volatile("cp.async.wait_group 0;");
        __syncthreads();

        uint32_t bo = sb + (ch & 1) * BUFB;
#pragma unroll
        for (int ks = 0; ks < 2; ks++) {
            int kc = ks * 16;
            uint32_t afh[2][4], afl[2][4];
#pragma unroll
            for (int mt = 0; mt < 2; mt++) {
                int row = warp_m * 32 + mt * 16 + a_r;
                uint32_t ad = bo + (uint32_t)(row * HPAD + kc + a_kg) * 2;
                LDSM4(afh[mt], ad + OAH);
                LDSM4(afl[mt], ad + OAL);
            }
#pragma unroll
            for (int np = 0; np < 4; np++) {
                uint32_t bfh[4], bfl[4];
                int nrow = warp_n * 64 + np * 16 + b_r;
                uint32_t bd = bo + (uint32_t)(nrow * HPAD + kc + b_kg) * 2;
                LDSM4(bfh, bd + OBH);
                LDSM4(bfl, bd + OBL);
#pragma unroll
                for (int mt = 0; mt < 2; mt++) {
                    MMA16816(acc[mt][np * 2 + 0], afh[mt], (&bfh[0]));
                    MMA16816(acc[mt][np * 2 + 1], afh[mt], (&bfh[2]));
                    MMA16816(acc[mt][np * 2 + 0], afl[mt], (&bfh[0]));
                    MMA16816(acc[mt][np * 2 + 1], afl[mt], (&bfh[2]));
                    MMA16816(acc[mt][np * 2 + 0], afh[mt], (&bfl[0]));
                    MMA16816(acc[mt][np * 2 + 1], afh[mt], (&bfl[2]));
                }
            }
            // issue next chunk's loads between the two compute halves
            if (ks == 0 && ch + 1 < nchunks) issue_chunk((ch + 1) & 1, (ch + 1) << 5);
        }
    }

    const int mrow = m0 + warp_m * 32;
    const int ncol = n0 + warp_n * 64;
#pragma unroll
    for (int mt = 0; mt < 2; mt++) {
#pragma unroll
        for (int nt = 0; nt < 8; nt++) {
            int c = ncol + nt * 8 + (lane & 3) * 2;
            float2 bv = bias ? *(const float2*)&bias[c] : make_float2(0.f, 0.f);
            int r0 = mrow + mt * 16 + (lane >> 2);
            if (r0 < M) {
                float2 v = make_float2(acc[mt][nt][0] + bv.x, acc[mt][nt][1] + bv.y);
                *(float2*)&C[(size_t)r0 * ldc + c] = v;
            }
            int r1 = r0 + 8;
            if (r1 < M) {
                float2 v = make_float2(acc[mt][nt][2] + bv.x, acc[mt][nt][3] + bv.y);
                *(float2*)&C[(size_t)r1 * ldc + c] = v;
            }
        }
    }
}

// ---------------- fp32 SGEMM (batched fp32-out / split-out) ----------------
template <int MODE>   // 0 = fp32 C, 1 = bf16 hi/lo split output
__device__ __forceinline__ void sgemm_body(
    const float* A, int lda, const float* B, int ldb, float* C, int ldc,
    int M, int N, int K, const float* bias,
    __nv_bfloat16* Hi, __nv_bfloat16* Lo)
{
    const int BM = 128, BN = 128, BK = 8;
    __shared__ float As[BK][BM];
    __shared__ float Bs[BK][BN];
    int tid = threadIdx.x;
    int brow = blockIdx.y, bcol = blockIdx.x;
    int aRow = tid >> 1, aCol4 = (tid & 1) * 4;
    int bRow = tid >> 5, bCol4 = (tid & 31) * 4;
    int tr = (tid >> 4) * 8, tc = (tid & 15) * 8;
    float acc[8][8];
#pragma unroll
    for (int i = 0; i < 8; i++)
#pragma unroll
        for (int j = 0; j < 8; j++) acc[i][j] = 0.f;
    int gArow = brow * BM + aRow;
    bool aValid = gArow < M;
    const float* Aptr = A + (long)(aValid ? gArow : 0) * lda + aCol4;
    const float* Bptr = B + (long)bRow * ldb + (long)bcol * BN + bCol4;
    for (int k0 = 0; k0 < K; k0 += BK) {
        float4 av = aValid ? *(const float4*)(Aptr + k0) : make_float4(0.f, 0.f, 0.f, 0.f);
        float4 bv = *(const float4*)(Bptr + (long)k0 * ldb);
        As[aCol4 + 0][aRow] = av.x; As[aCol4 + 1][aRow] = av.y;
        As[aCol4 + 2][aRow] = av.z; As[aCol4 + 3][aRow] = av.w;
        *(float4*)&Bs[bRow][bCol4] = bv;
        __syncthreads();
#pragma unroll
        for (int kk = 0; kk < BK; kk++) {
            float ar[8], br[8];
#pragma unroll
            for (int i = 0; i < 8; i++) ar[i] = As[kk][tr + i];
#pragma unroll
            for (int j = 0; j < 8; j++) br[j] = Bs[kk][tc + j];
#pragma unroll
            for (int i = 0; i < 8; i++)
#pragma unroll
                for (int j = 0; j < 8; j++)
                    acc[i][j] = fmaf(ar[i], br[j], acc[i][j]);
        }
        __syncthreads();
    }
#pragma unroll
    for (int i = 0; i < 8; i++) {
        int row = brow * BM + tr + i;
        if (row < M) {
#pragma unroll
            for (int j = 0; j < 8; j += 4) {
                int col = bcol * BN + tc + j;
                float4 v;
                v.x = acc[i][j + 0] + (bias ? bias[col + 0] : 0.f);
                v.y = acc[i][j + 1] + (bias ? bias[col + 1] : 0.f);
                v.z = acc[i][j + 2] + (bias ? bias[col + 2] : 0.f);
                v.w = acc[i][j + 3] + (bias ? bias[col + 3] : 0.f);
                if (MODE == 0) {
                    *(float4*)&C[(long)row * ldc + col] = v;
                } else {
                    __nv_bfloat16 h0, l0, h1, l1, h2, l2, h3, l3;
                    split1(v.x, h0, l0); split1(v.y, h1, l1);
                    split1(v.z, h2, l2); split1(v.w, h3, l3);
                    __nv_bfloat162 hp0; hp0.x = h0; hp0.y = h1;
                    __nv_bfloat162 hp1; hp1.x = h2; hp1.y = h3;
                    __nv_bfloat162 lp0; lp0.x = l0; lp0.y = l1;
                    __nv_bfloat162 lp1; lp1.x = l2; lp1.y = l3;
                    long o = (long)row * ldc + col;
                    *(__nv_bfloat162*)&Hi[o]     = hp0;
                    *(__nv_bfloat162*)&Hi[o + 2] = hp1;
                    *(__nv_bfloat162*)&Lo[o]     = lp0;
                    *(__nv_bfloat162*)&Lo[o + 2] = lp1;
                }
            }
        }
    }
}

__global__ void __launch_bounds__(256) sgemm_split_kernel(
    const float* __restrict__ A, int lda,
    const float* __restrict__ B, int ldb,
    int M, int N, int K, const float* __restrict__ bias,
    __nv_bfloat16* __restrict__ Hi, __nv_bfloat16* __restrict__ Lo)
{
    sgemm_body<1>(A, lda, B, ldb, nullptr, N, M, N, K, bias, Hi, Lo);
}

__global__ void __launch_bounds__(256) sgemm_batched_kernel(
    const float* __restrict__ A, int lda, long strideA,
    const float* __restrict__ B, int ldb, long strideB,
    float* __restrict__ C, int ldc, long strideC,
    int M, int N, int K)
{
    int l = blockIdx.z;
    sgemm_body<0>(A + (long)l * strideA, lda, B + (long)l * strideB, ldb,
                  C + (long)l * strideC, ldc, M, N, K, nullptr, nullptr, nullptr);
}

// ---------------- small helper kernels ----------------
__global__ void count_kernel(const int* __restrict__ dst, int n) {
    int i = blockIdx.x * blockDim.x + threadIdx.x;
    if (i < n) atomicAdd(&d_deg[dst[i]], 1);
}

__global__ void scan_kernel() {
    __shared__ int sh[1024];
    __shared__ int carry;
    if (threadIdx.x == 0) carry = 0;
    __syncthreads();
    for (int base = 0; base < NN; base += 1024) {
        int i = base + (int)threadIdx.x;
        int v = (i < NN) ? d_deg[i] : 0;
        sh[threadIdx.x] = v;
        __syncthreads();
        for (int off = 1; off < 1024; off <<= 1) {
            int t = (threadIdx.x >= (unsigned)off) ? sh[threadIdx.x - off] : 0;
            __syncthreads();
            sh[threadIdx.x] += t;
            __syncthreads();
        }
        if (i < NN) d_offs[i] = carry + sh[threadIdx.x] - v;
        __syncthreads();
        if (threadIdx.x == 1023) carry += sh[1023];
        __syncthreads();
    }
    if (threadIdx.x == 0) d_offs[NN] = carry;
}

// scatter CSR: srcp + permuted eattr rows in one pass
__global__ void scatter_kernel(const int* __restrict__ src, const int* __restrict__ dst,
                               const float* __restrict__ ea, int n) {
    int i = blockIdx.x * blockDim.x + threadIdx.x;
    if (i < n) {
        int pos = atomicAdd(&d_cnt[dst[i]], 1);
        d_srcp[pos] = src[i];
        const float4* s = (const float4*)(ea + (size_t)i * EIN);
        float4* d = (float4*)(d_eap + (size_t)pos * EIN);
        d[0] = s[0]; d[1] = s[1]; d[2] = s[2]; d[3] = s[3];
    }
}

__global__ void logdeg_sum_kernel() {
    __shared__ float sh[256];
    float s = 0.f;
    for (int i = blockIdx.x * blockDim.x + threadIdx.x; i < NN; i += gridDim.x * blockDim.x)
        s += log1pf((float)d_deg[i]);
    sh[threadIdx.x] = s;
    __syncthreads();
    for (int off = 128; off > 0; off >>= 1) {
        if (threadIdx.x < (unsigned)off) sh[threadIdx.x] += sh[threadIdx.x + off];
        __syncthreads();
    }
    if (threadIdx.x == 0) atomicAdd(&d_avg[0], sh[0]);
}

__global__ void scalers_kernel() {
    int i = blockIdx.x * blockDim.x + threadIdx.x;
    if (i < NN) {
        float avg  = d_avg[0] / (float)NN;
        float degc = fmaxf((float)d_deg[i], 1.f);
        float l    = logf(degc + 1.f);
        d_amp[i] = l / avg;
        d_att[i] = avg / l;
    }
}

// batched vecmat over blockIdx.x = layer; writes into arbitrary strided output
__global__ void vecmatb_kernel(const float* __restrict__ v, long sv,
                               const float* __restrict__ W, int ldw, long sw,
                               const float* __restrict__ badd, long sb,
                               float* __restrict__ out, long so) {
    int l = blockIdx.x, c = threadIdx.x;
    const float* vl = v + l * sv;
    const float* Wl = W + l * sw;
    float s = 0.f;
    for (int j = 0; j < HH; j++) s = fmaf(vl[j], Wl[j * ldw + c], s);
    out[l * so + c] = s + badd[l * sb + c];
}

// Wc [384,128] from preW (W0,W1) and Y rows 0..127 (Q0); batched over z
__global__ void wconv_kernel(const float* __restrict__ preW) {
    int l = blockIdx.z;
    int i = blockIdx.x * blockDim.x + threadIdx.x;   // 384*128
    if (i >= 384 * 128) return;
    int n = i >> 7, k = i & 127;
    float v;
    if (n < 256) {
        int c = n & 127;
        v = preW[(size_t)l * 3 * HH * HH + ((n >> 7) ? HH * HH : 0) + k * HH + c];
    } else {
        v = d_Y[(size_t)l * 13 * HH * HH + (size_t)k * HH + (n - 256)];
    }
    __nv_bfloat16 h, lo; split1(v, h, lo);
    size_t o = (size_t)l * 3 * HH * HH + (size_t)n * HH + k;
    d_Wch[o] = h; d_Wcl[o] = lo;
}

// Qc [384,512] from Y rows 128..1663; batched over z
__global__ void qconv_kernel() {
    int l = blockIdx.z;
    int i = blockIdx.x * blockDim.x + threadIdx.x;   // 384*512
    if (i >= 384 * 512) return;
    int n = i >> 9, k = i & 511;
    int q = n >> 7, c = n & 127;
    float v = d_Y[(size_t)l * 13 * HH * HH + (size_t)(128 + q * 512 + k) * HH + c];
    __nv_bfloat16 h, lo; split1(v, h, lo);
    size_t o = (size_t)l * 384 * 512 + (size_t)n * 512 + k;
    d_Qch[o] = h; d_Qcl[o] = lo;
}

// per-edge message value for column c (16 FMAs against S registers)
__device__ __forceinline__ float edge_msg(int r, const float* Sreg, float base) {
    const float4* ea = (const float4*)(d_eap + (size_t)r * EIN);
    float4 e0 = ea[0], e1 = ea[1], e2 = ea[2], e3 = ea[3];
    float v = base;
    v = fmaf(e0.x, Sreg[0],  v); v = fmaf(e0.y, Sreg[1],  v);
    v = fmaf(e0.z, Sreg[2],  v); v = fmaf(e0.w, Sreg[3],  v);
    v = fmaf(e1.x, Sreg[4],  v); v = fmaf(e1.y, Sreg[5],  v);
    v = fmaf(e1.z, Sreg[6],  v); v = fmaf(e1.w, Sreg[7],  v);
    v = fmaf(e2.x, Sreg[8],  v); v = fmaf(e2.y, Sreg[9],  v);
    v = fmaf(e2.z, Sreg[10], v); v = fmaf(e2.w, Sreg[11], v);
    v = fmaf(e3.x, Sreg[12], v); v = fmaf(e3.y, Sreg[13], v);
    v = fmaf(e3.z, Sreg[14], v); v = fmaf(e3.w, Sreg[15], v);
    return v;
}

// segmented aggregation, grid-stride over nodes; 2-edge unroll (validated optimum).
__global__ void __launch_bounds__(128) agg_kernel(const float* __restrict__ S) {
    int c = threadIdx.x;
    float Sreg[16];
#pragma unroll
    for (int k = 0; k < 16; k++) Sreg[k] = S[k * HH + c];
    for (int node = blockIdx.x; node < NN; node += gridDim.x) {
        int s = d_offs[node], e = d_offs[node + 1];
        float hd = d_cmb[(size_t)node * 384 + c];
        float sum = 0.f, ss = 0.f, mn = INFINITY, mx = -INFINITY;
        int r = s;
        for (; r + 2 <= e; r += 2) {
            int sp0 = d_srcp[r], sp1 = d_srcp[r + 1];
            float hs0 = d_cmb[(size_t)sp0 * 384 + 128 + c];
            float hs1 = d_cmb[(size_t)sp1 * 384 + 128 + c];
            float v0 = edge_msg(r,     Sreg, hd + hs0);
            float v1 = edge_msg(r + 1, Sreg, hd + hs1);
            sum += v0; ss = fmaf(v0, v0, ss);
            mn = fminf(mn, v0); mx = fmaxf(mx, v0);
            sum += v1; ss = fmaf(v1, v1, ss);
            mn = fminf(mn, v1); mx = fmaxf(mx, v1);
        }
        if (r < e) {
            int sp = d_srcp[r];
            float v = edge_msg(r, Sreg, hd + d_cmb[(size_t)sp * 384 + 128 + c]);
            sum += v; ss = fmaf(v, v, ss);
            mn = fminf(mn, v); mx = fmaxf(mx, v);
        }
        float deg  = (float)(e - s);
        float degc = fmaxf(deg, 1.f);
        float mean = sum / degc;
        float var  = ss / degc - mean * mean;
        float sd   = sqrtf(fmaxf(var, 0.f) + 1e-5f);
        if (e == s) { mn = 0.f; mx = 0.f; }
        size_t o = (size_t)node * 512;
        __nv_bfloat16 h, l;
        split1(mean, h, l); d_agh[o +       c] = h; d_agl[o +       c] = l;
        split1(mn,   h, l); d_agh[o + 128 + c] = h; d_agl[o + 128 + c] = l;
        split1(mx,   h, l); d_agh[o + 256 + c] = h; d_agl[o + 256 + c] = l;
        split1(sd,   h, l); d_agh[o + 384 + c] = h; d_agl[o + 384 + c] = l;
    }
}

// h_next = relu(z(+b2) + y0 + amp*y1 + att*y2); writes bf16 splits only
__global__ void combine_kernel(__nv_bfloat16* __restrict__ hh, __nv_bfloat16* __restrict__ hl) {
    int i = blockIdx.x * blockDim.x + threadIdx.x;   // NN*32 threads, 4 cols each
    if (i >= NN * 32) return;
    int node = i >> 5, c = (i & 31) * 4;
    size_t co = (size_t)node * 384;
    float4 zv = *(const float4*)&d_cmb[co + 256 + c];
    float4 y0 = *(const float4*)&d_y[co + c];
    float4 y1 = *(const float4*)&d_y[co + 128 + c];
    float4 y2 = *(const float4*)&d_y[co + 256 + c];
    float amp = d_amp[node], att = d_att[node];
    float v0 = fmaxf(zv.x + y0.x + amp * y1.x + att * y2.x, 0.f);
    float v1 = fmaxf(zv.y + y0.y + amp * y1.y + att * y2.y, 0.f);
    float v2 = fmaxf(zv.z + y0.z + amp * y1.z + att * y2.z, 0.f);
    float v3 = fmaxf(zv.w + y0.w + amp * y1.w + att * y2.w, 0.f);
    __nv_bfloat16 h0, l0, h1, l1, h2, l2, h3, l3;
    split1(v0, h0, l0); split1(v1, h1, l1); split1(v2, h2, l2); split1(v3, h3, l3);
    __nv_bfloat162 hp0; hp0.x = h0; hp0.y = h1;
    __nv_bfloat162 hp1; hp1.x = h2; hp1.y = h3;
    __nv_bfloat162 lp0; lp0.x = l0; lp0.y = l1;
    __nv_bfloat162 lp1; lp1.x = l2; lp1.y = l3;
    size_t o = (size_t)node * HH + c;
    *(__nv_bfloat162*)&hh[o]     = hp0;
    *(__nv_bfloat162*)&hh[o + 2] = hp1;
    *(__nv_bfloat162*)&hl[o]     = lp0;
    *(__nv_bfloat162*)&hl[o + 2] = lp1;
}

// pool from bf16 splits (h = hi + lo)
__global__ void pool_kernel(const __nv_bfloat16* __restrict__ hh,
                            const __nv_bfloat16* __restrict__ hl,
                            const int* __restrict__ batch) {
    int i = blockIdx.x * blockDim.x + threadIdx.x;
    if (i >= NN * HH) return;
    int node = i >> 7, c = i & 127;
    float h = __bfloat162float(hh[i]) + __bfloat162float(hl[i]);
    atomicAdd(&d_g[batch[node] * HH + c], h);
}

__global__ void head_kernel(const float* __restrict__ W, const float* __restrict__ b,
                            float* __restrict__ out) {
    __shared__ float sh[HH];
    sh[threadIdx.x] = d_g[blockIdx.x * HH + threadIdx.x];
    __syncthreads();
    if (threadIdx.x < OUTC) {
        float s = b[threadIdx.x];
        for (int k = 0; k < HH; k++) s = fmaf(sh[k], W[k * OUTC + threadIdx.x], s);
        out[blockIdx.x * OUTC + threadIdx.x] = s;
    }
}

// ---------------- host orchestration ----------------
static void gemm_b(const float* A, int lda, long sA, const float* B, int ldb, long sB,
                   float* C, int ldc, long sC, int M, int N, int K) {
    dim3 grid(N / 128, (M + 127) / 128, LL);
    sgemm_batched_kernel<<<grid, 256>>>(A, lda, sA, B, ldb, sB, C, ldc, sC, M, N, K);
}

static void tgemm(const __nv_bfloat16* Ah, const __nv_bfloat16* Al,
                  const __nv_bfloat16* Bh, const __nv_bfloat16* Bl,
                  float* C, int ldc, int M, int N, int K, const float* bias) {
    dim3 grid((M + 127) / 128, N / 128);
    hmma_kernel<<<grid, 256, TSMEM>>>(Ah, Al, Bh, Bl, C, ldc, M, K, bias);
}

template <typename T>
static T* sym(const void* symbol) {
    void* p = nullptr;
    cudaGetSymbolAddress(&p, symbol);
    return (T*)p;
}

extern "C" void kernel_launch(void* const* d_in, const int* in_sizes, int n_in,
                              void* d_out, int out_size) {
    const float* x     = (const float*)d_in[0];
    const float* eattr = (const float*)d_in[1];
    const int*   src   = (const int*)  d_in[2];
    const int*   dst   = (const int*)  d_in[3];
    const int*   batch = (const int*)  d_in[4];
    const float* nW    = (const float*)d_in[5];
    const float* nb    = (const float*)d_in[6];
    const float* eW    = (const float*)d_in[7];
    const float* eb    = (const float*)d_in[8];
    const float* encW  = (const float*)d_in[9];
    const float* encb  = (const float*)d_in[10];
    const float* preW  = (const float*)d_in[11];
    const float* preb  = (const float*)d_in[12];
    const float* postW = (const float*)d_in[13];
    const float* postb = (const float*)d_in[14];
    const float* linW  = (const float*)d_in[15];
    const float* linb  = (const float*)d_in[16];
    const float* headW = (const float*)d_in[17];
    const float* headb = (const float*)d_in[18];
    float* out = (float*)d_out;

    float* cmb  = sym<float>(d_cmb);
    __nv_bfloat16* agh = sym<__nv_bfloat16>(d_agh);
    __nv_bfloat16* agl = sym<__nv_bfloat16>(d_agl);
    float* y    = sym<float>(d_y);
    __nv_bfloat16* hh[2] = { sym<__nv_bfloat16>(d_hh0), sym<__nv_bfloat16>(d_hh1) };
    __nv_bfloat16* hl[2] = { sym<__nv_bfloat16>(d_hl0), sym<__nv_bfloat16>(d_hl1) };
    int*   deg  = sym<int>(d_deg);
    int*   offs = sym<int>(d_offs);
    int*   cnt  = sym<int>(d_cnt);
    float* avg  = sym<float>(d_avg);
    float* S    = sym<float>(d_S);
    float* T1   = sym<float>(d_T1);
    float* uv   = sym<float>(d_uv);
    float* Yb   = sym<float>(d_Y);
    float* cbias= sym<float>(d_cbias);
    float* g    = sym<float>(d_g);
    __nv_bfloat16* Wch = sym<__nv_bfloat16>(d_Wch); __nv_bfloat16* Wcl = sym<__nv_bfloat16>(d_Wcl);
    __nv_bfloat16* Qch = sym<__nv_bfloat16>(d_Qch); __nv_bfloat16* Qcl = sym<__nv_bfloat16>(d_Qcl);

    cudaFuncSetAttribute(hmma_kernel, cudaFuncAttributeMaxDynamicSharedMemorySize, TSMEM);

    const int TPB = 256;

    // ---- graph structure ----
    cudaMemsetAsync(deg, 0, NN * sizeof(int), 0);
    cudaMemsetAsync(avg, 0, sizeof(float), 0);
    cudaMemsetAsync(cbias, 0, LL * 3 * HH * sizeof(float), 0);
    count_kernel<<<(EE + TPB - 1) / TPB, TPB>>>(dst, EE);
    scan_kernel<<<1, 1024>>>();
    cudaMemcpyAsync(cnt, offs, NN * sizeof(int), cudaMemcpyDeviceToDevice, 0);
    scatter_kernel<<<(EE + TPB - 1) / TPB, TPB>>>(src, dst, eattr, EE);
    logdeg_sum_kernel<<<256, 256>>>();
    scalers_kernel<<<(NN + TPB - 1) / TPB, TPB>>>();

    // ---- node embedding: GEMM straight into bf16 splits ----
    {
        dim3 grid(HH / 128, (NN + 127) / 128);
        sgemm_split_kernel<<<grid, 256>>>(x, FIN, nW, HH, NN, HH, FIN, nb, hh[0], hl[0]);
    }

    // ---- batched per-layer weight precompute ----
    gemm_b(eW, HH, 0, encW, HH, (long)HH * HH, T1, HH, (long)EIN * HH, EIN, HH, HH);
    gemm_b(T1, HH, (long)EIN * HH, preW + 2 * HH * HH, HH, (long)3 * HH * HH,
           S, HH, (long)EIN * HH, EIN, HH, HH);
    gemm_b(postW, HH, (long)13 * HH * HH, linW, HH, (long)HH * HH,
           Yb, HH, (long)13 * HH * HH, 13 * HH, HH, HH);
    vecmatb_kernel<<<LL, HH>>>(eb, 0, encW, HH, (long)HH * HH, encb, HH, uv, HH);
    vecmatb_kernel<<<LL, HH>>>(uv, HH, preW + 2 * HH * HH, HH, (long)3 * HH * HH,
                               preb, HH, cbias, 3 * HH);
    vecmatb_kernel<<<LL, HH>>>(postb, HH, linW, HH, (long)HH * HH,
                               linb, HH, cbias + 256, 3 * HH);
    {
        dim3 gw((384 * 128 + TPB - 1) / TPB, 1, LL);
        wconv_kernel<<<gw, TPB>>>(preW);
        dim3 gq((384 * 512 + TPB - 1) / TPB, 1, LL);
        qconv_kernel<<<gq, TPB>>>();
    }

    // ---- layers ----
    int cb = 0;
    for (int l = 0; l < LL; l++) {
        // cmb = h @ [W0 | W1 | Q0] + [tl|0|b2]  -> [hd+tl | hs | z+b2], N=384
        tgemm(hh[cb], hl[cb], Wch + (size_t)l * 3 * HH * HH, Wcl + (size_t)l * 3 * HH * HH,
              cmb, 3 * HH, NN, 3 * HH, HH, cbias + l * 3 * HH);
        // segmented aggregation with fused rank-16 edge message -> agg splits [N,512]
        agg_kernel<<<4096, 128>>>(S + (size_t)l * EIN * HH);
        // y = agg @ Qcat_l  [N,384]
        tgemm(agh, agl, Qch + (size_t)l * 384 * 512, Qcl + (size_t)l * 384 * 512,
              y, 3 * HH, NN, 3 * HH, 4 * HH, nullptr);
        // combine -> splits only
        combine_kernel<<<(NN * 32 + TPB - 1) / TPB, TPB>>>(hh[cb ^ 1], hl[cb ^ 1]);
        cb ^= 1;
    }

    // ---- pool + head ----
    cudaMemsetAsync(g, 0, GG * HH * sizeof(float), 0);
    pool_kernel<<<(NN * HH + TPB - 1) / TPB, TPB>>>(hh[cb], hl[cb], batch);
    head_kernel<<<GG, HH>>>(headW, headb, out);
}

// round 16
// speedup vs baseline: 1.0562x; 1.0019x over previous
#include <cuda_runtime.h>
#include <math.h>
#include <stdint.h>
#include <cuda_bf16.h>

// ---------------- problem constants ----------------
static const int NN   = 50000;   // nodes
static const int EE   = 400000;  // edges
static const int FIN  = 64;
static const int EIN  = 16;
static const int HH   = 128;
static const int LL   = 4;
static const int GG   = 256;
static const int OUTC = 12;

// ---------------- scratch (static device globals; no runtime alloc) ----------------
__device__ float d_eap[(size_t)EE * EIN];       // permuted raw edge attrs (CSR order)
__device__ float d_cmb[(size_t)NN * 3 * HH];    // [hd+tl | hs | z+b2] per node
__device__ __nv_bfloat16 d_agh[(size_t)NN * 4 * HH];
__device__ __nv_bfloat16 d_agl[(size_t)NN * 4 * HH];
__device__ float d_y  [(size_t)NN * 3 * HH];    // agg @ Qcat
__device__ __nv_bfloat16 d_hh0[(size_t)NN * HH];
__device__ __nv_bfloat16 d_hl0[(size_t)NN * HH];
__device__ __nv_bfloat16 d_hh1[(size_t)NN * HH];
__device__ __nv_bfloat16 d_hl1[(size_t)NN * HH];
__device__ int   d_deg [NN];
__device__ int   d_offs[NN + 1];
__device__ int   d_cnt [NN];
__device__ int   d_srcp[EE];
__device__ float d_amp[NN];
__device__ float d_att[NN];
__device__ float d_avg[1];
__device__ float d_S   [LL * EIN * HH];         // eW@Wenc@Wpre2 per layer [16,128]
__device__ float d_T1  [LL * EIN * HH];         // temp (batched)
__device__ float d_uv  [LL * HH];               // temp (batched)
__device__ float d_Y   [(size_t)LL * 13 * HH * HH]; // [P0|P1..P12]@lin per layer [1664,128]
__device__ float d_cbias[LL * 3 * HH];          // [tl | 0 | b2] per layer
__device__ float d_g   [GG * HH];
// transposed bf16-split weights (Bt layout: [N,K] row-major)
__device__ __nv_bfloat16 d_Wch[LL * 3 * HH * HH], d_Wcl[LL * 3 * HH * HH];   // [384,128]: W0|W1|Q0
__device__ __nv_bfloat16 d_Qch[LL * 3 * HH * 4 * HH], d_Qcl[LL * 3 * HH * 4 * HH]; // [384,512]

// ================= common MMA helpers =================
static const int HPAD = 40;                 // padded K-stride in bf16 (conflict-free ldmatrix)

#define LDSM4(R, ADDR) \
    asm volatile("ldmatrix.sync.aligned.m8n8.x4.shared.b16 {%0,%1,%2,%3}, [%4];" \
        : "=r"((R)[0]), "=r"((R)[1]), "=r"((R)[2]), "=r"((R)[3]) : "r"(ADDR))

#define MMA16816(D, A, B) \
    asm volatile("mma.sync.aligned.m16n8k16.row.col.f32.bf16.bf16.f32 " \
        "{%0,%1,%2,%3}, {%4,%5,%6,%7}, {%8,%9}, {%0,%1,%2,%3};" \
        : "+f"((D)[0]), "+f"((D)[1]), "+f"((D)[2]), "+f"((D)[3]) \
        : "r"((A)[0]), "r"((A)[1]), "r"((A)[2]), "r"((A)[3]), "r"((B)[0]), "r"((B)[1]))

__device__ __forceinline__ uint32_t smem_u32(const void* p) {
    uint32_t a;
    asm("{ .reg .u64 t; cvta.to.shared.u64 t, %1; cvt.u32.u64 %0, t; }" : "=r"(a) : "l"(p));
    return a;
}

__device__ __forceinline__ void split1(float x, __nv_bfloat16& h, __nv_bfloat16& l) {
    h = __float2bfloat16(x);
    l = __float2bfloat16(x - __bfloat162float(h));
}

// ================= bf16x3 GEMM (mma.sync, 128x128 tile, 2 CTA/SM) =================
// Single barrier per K-chunk: wait -> barrier -> compute(ks=0) -> issue(ch+1) -> compute(ks=1).
static const int TILEB = 128 * HPAD * 2;    // 10240 B per tile
static const int BUFB  = 4 * TILEB;         // Ah,Al,Bh,Bl
static const int TSMEM = 2 * BUFB;          // 81920 B

__global__ void __launch_bounds__(256, 2) hmma_kernel(
    const __nv_bfloat16* __restrict__ Ah, const __nv_bfloat16* __restrict__ Al,
    const __nv_bfloat16* __restrict__ Bh, const __nv_bfloat16* __restrict__ Bl,
    float* __restrict__ C, int ldc, int M, int K,
    const float* __restrict__ bias)
{
    extern __shared__ char smem[];
    const uint32_t sb = smem_u32(smem);
    const int tid = threadIdx.x, lane = tid & 31, wid = tid >> 5;
    const int warp_m = wid & 3, warp_n = wid >> 2;         // 4 x 2 warps
    const int m0 = blockIdx.x * 128, n0 = blockIdx.y * 128;

    const int OAH = 0, OAL = TILEB, OBH = 2 * TILEB, OBL = 3 * TILEB;

    float acc[2][8][4];
#pragma unroll
    for (int i = 0; i < 2; i++)
#pragma unroll
        for (int j = 0; j < 8; j++)
#pragma unroll
            for (int k = 0; k < 4; k++) acc[i][j][k] = 0.f;

    const int ldr = tid >> 2;
    const int ldc8 = (tid & 3) * 8;
    auto issue_chunk = [&](int buf, int k0) {
        uint32_t bo = sb + buf * BUFB;
#pragma unroll
        for (int half = 0; half < 2; half++) {
            int r = half * 64 + ldr;
            uint32_t soff = (uint32_t)(r * HPAD + ldc8) * 2;
            int arow = m0 + r;
            int asz = (arow < M) ? 16 : 0;
            const void* gah = Ah + (size_t)arow * K + k0 + ldc8;
            const void* gal = Al + (size_t)arow * K + k0 + ldc8;
            asm volatile("cp.async.cg.shared.global [%0], [%1], 16, %2;"
                         :: "r"(bo + OAH + soff), "l"(gah), "r"(asz));
            asm volatile("cp.async.cg.shared.global [%0], [%1], 16, %2;"
                         :: "r"(bo + OAL + soff), "l"(gal), "r"(asz));
            const void* gbh = Bh + (size_t)(n0 + r) * K + k0 + ldc8;
            const void* gbl = Bl + (size_t)(n0 + r) * K + k0 + ldc8;
            asm volatile("cp.async.cg.shared.global [%0], [%1], 16;"
                         :: "r"(bo + OBH + soff), "l"(gbh));
            asm volatile("cp.async.cg.shared.global [%0], [%1], 16;"
                         :: "r"(bo + OBL + soff), "l"(gbl));
        }
        asm volatile("cp.async.commit_group;");
    };

    const int a_r  = lane & 15;
    const int a_kg = (lane >> 4) * 8;
    const int b_r  = (lane & 7) + ((lane >> 4) * 8);
    const int b_kg = ((lane >> 3) & 1) * 8;

    const int nchunks = K >> 5;
    issue_chunk(0, 0);

    for (int ch = 0; ch < nchunks; ch++) {
        asm volatile("cp.async.wait_group 0;");
        __syncthreads();

        uint32_t bo = sb + (ch & 1) * BUFB;
#pragma unroll
        for (int ks = 0; ks < 2; ks++) {
            int kc = ks * 16;
            uint32_t afh[2][4], afl[2][4];
#pragma unroll
            for (int mt = 0; mt < 2; mt++) {
                int row = warp_m * 32 + mt * 16 + a_r;
                uint32_t ad = bo + (uint32_t)(row * HPAD + kc + a_kg) * 2;
                LDSM4(afh[mt], ad + OAH);
                LDSM4(afl[mt], ad + OAL);
            }
#pragma unroll
            for (int np = 0; np < 4; np++) {
                uint32_t bfh[4], bfl[4];
                int nrow = warp_n * 64 + np * 16 + b_r;
                uint32_t bd = bo + (uint32_t)(nrow * HPAD + kc + b_kg) * 2;
                LDSM4(bfh, bd + OBH);
                LDSM4(bfl, bd + OBL);
#pragma unroll
                for (int mt = 0; mt < 2; mt++) {
                    MMA16816(acc[mt][np * 2 + 0], afh[mt], (&bfh[0]));
                    MMA16816(acc[mt][np * 2 + 1], afh[mt], (&bfh[2]));
                    MMA16816(acc[mt][np * 2 + 0], afl[mt], (&bfh[0]));
                    MMA16816(acc[mt][np * 2 + 1], afl[mt], (&bfh[2]));
                    MMA16816(acc[mt][np * 2 + 0], afh[mt], (&bfl[0]));
                    MMA16816(acc[mt][np * 2 + 1], afh[mt], (&bfl[2]));
                }
            }
            if (ks == 0 && ch + 1 < nchunks) issue_chunk((ch + 1) & 1, (ch + 1) << 5);
        }
    }

    const int mrow = m0 + warp_m * 32;
    const int ncol = n0 + warp_n * 64;
#pragma unroll
    for (int mt = 0; mt < 2; mt++) {
#pragma unroll
        for (int nt = 0; nt < 8; nt++) {
            int c = ncol + nt * 8 + (lane & 3) * 2;
            float2 bv = bias ? *(const float2*)&bias[c] : make_float2(0.f, 0.f);
            int r0 = mrow + mt * 16 + (lane >> 2);
            if (r0 < M) {
                float2 v = make_float2(acc[mt][nt][0] + bv.x, acc[mt][nt][1] + bv.y);
                *(float2*)&C[(size_t)r0 * ldc + c] = v;
            }
            int r1 = r0 + 8;
            if (r1 < M) {
                float2 v = make_float2(acc[mt][nt][2] + bv.x, acc[mt][nt][3] + bv.y);
                *(float2*)&C[(size_t)r1 * ldc + c] = v;
            }
        }
    }
}

// ---------------- fp32 SGEMM (batched fp32-out / split-out) ----------------
template <int MODE>   // 0 = fp32 C, 1 = bf16 hi/lo split output
__device__ __forceinline__ void sgemm_body(
    const float* A, int lda, const float* B, int ldb, float* C, int ldc,
    int M, int N, int K, const float* bias,
    __nv_bfloat16* Hi, __nv_bfloat16* Lo)
{
    const int BM = 128, BN = 128, BK = 8;
    __shared__ float As[BK][BM];
    __shared__ float Bs[BK][BN];
    int tid = threadIdx.x;
    int brow = blockIdx.y, bcol = blockIdx.x;
    int aRow = tid >> 1, aCol4 = (tid & 1) * 4;
    int bRow = tid >> 5, bCol4 = (tid & 31) * 4;
    int tr = (tid >> 4) * 8, tc = (tid & 15) * 8;
    float acc[8][8];
#pragma unroll
    for (int i = 0; i < 8; i++)
#pragma unroll
        for (int j = 0; j < 8; j++) acc[i][j] = 0.f;
    int gArow = brow * BM + aRow;
    bool aValid = gArow < M;
    const float* Aptr = A + (long)(aValid ? gArow : 0) * lda + aCol4;
    const float* Bptr = B + (long)bRow * ldb + (long)bcol * BN + bCol4;
    for (int k0 = 0; k0 < K; k0 += BK) {
        float4 av = aValid ? *(const float4*)(Aptr + k0) : make_float4(0.f, 0.f, 0.f, 0.f);
        float4 bv = *(const float4*)(Bptr + (long)k0 * ldb);
        As[aCol4 + 0][aRow] = av.x; As[aCol4 + 1][aRow] = av.y;
        As[aCol4 + 2][aRow] = av.z; As[aCol4 + 3][aRow] = av.w;
        *(float4*)&Bs[bRow][bCol4] = bv;
        __syncthreads();
#pragma unroll
        for (int kk = 0; kk < BK; kk++) {
            float ar[8], br[8];
#pragma unroll
            for (int i = 0; i < 8; i++) ar[i] = As[kk][tr + i];
#pragma unroll
            for (int j = 0; j < 8; j++) br[j] = Bs[kk][tc + j];
#pragma unroll
            for (int i = 0; i < 8; i++)
#pragma unroll
                for (int j = 0; j < 8; j++)
                    acc[i][j] = fmaf(ar[i], br[j], acc[i][j]);
        }
        __syncthreads();
    }
#pragma unroll
    for (int i = 0; i < 8; i++) {
        int row = brow * BM + tr + i;
        if (row < M) {
#pragma unroll
            for (int j = 0; j < 8; j += 4) {
                int col = bcol * BN + tc + j;
                float4 v;
                v.x = acc[i][j + 0] + (bias ? bias[col + 0] : 0.f);
                v.y = acc[i][j + 1] + (bias ? bias[col + 1] : 0.f);
                v.z = acc[i][j + 2] + (bias ? bias[col + 2] : 0.f);
                v.w = acc[i][j + 3] + (bias ? bias[col + 3] : 0.f);
                if (MODE == 0) {
                    *(float4*)&C[(long)row * ldc + col] = v;
                } else {
                    __nv_bfloat16 h0, l0, h1, l1, h2, l2, h3, l3;
                    split1(v.x, h0, l0); split1(v.y, h1, l1);
                    split1(v.z, h2, l2); split1(v.w, h3, l3);
                    __nv_bfloat162 hp0; hp0.x = h0; hp0.y = h1;
                    __nv_bfloat162 hp1; hp1.x = h2; hp1.y = h3;
                    __nv_bfloat162 lp0; lp0.x = l0; lp0.y = l1;
                    __nv_bfloat162 lp1; lp1.x = l2; lp1.y = l3;
                    long o = (long)row * ldc + col;
                    *(__nv_bfloat162*)&Hi[o]     = hp0;
                    *(__nv_bfloat162*)&Hi[o + 2] = hp1;
                    *(__nv_bfloat162*)&Lo[o]     = lp0;
                    *(__nv_bfloat162*)&Lo[o + 2] = lp1;
                }
            }
        }
    }
}

__global__ void __launch_bounds__(256) sgemm_split_kernel(
    const float* __restrict__ A, int lda,
    const float* __restrict__ B, int ldb,
    int M, int N, int K, const float* __restrict__ bias,
    __nv_bfloat16* __restrict__ Hi, __nv_bfloat16* __restrict__ Lo)
{
    sgemm_body<1>(A, lda, B, ldb, nullptr, N, M, N, K, bias, Hi, Lo);
}

__global__ void __launch_bounds__(256) sgemm_batched_kernel(
    const float* __restrict__ A, int lda, long strideA,
    const float* __restrict__ B, int ldb, long strideB,
    float* __restrict__ C, int ldc, long strideC,
    int M, int N, int K)
{
    int l = blockIdx.z;
    sgemm_body<0>(A + (long)l * strideA, lda, B + (long)l * strideB, ldb,
                  C + (long)l * strideC, ldc, M, N, K, nullptr, nullptr, nullptr);
}

// ---------------- small helper kernels ----------------
__global__ void count_kernel(const int* __restrict__ dst, int n) {
    int i = blockIdx.x * blockDim.x + threadIdx.x;
    if (i < n) atomicAdd(&d_deg[dst[i]], 1);
}

__global__ void scan_kernel() {
    __shared__ int sh[1024];
    __shared__ int carry;
    if (threadIdx.x == 0) carry = 0;
    __syncthreads();
    for (int base = 0; base < NN; base += 1024) {
        int i = base + (int)threadIdx.x;
        int v = (i < NN) ? d_deg[i] : 0;
        sh[threadIdx.x] = v;
        __syncthreads();
        for (int off = 1; off < 1024; off <<= 1) {
            int t = (threadIdx.x >= (unsigned)off) ? sh[threadIdx.x - off] : 0;
            __syncthreads();
            sh[threadIdx.x] += t;
            __syncthreads();
        }
        if (i < NN) d_offs[i] = carry + sh[threadIdx.x] - v;
        __syncthreads();
        if (threadIdx.x == 1023) carry += sh[1023];
        __syncthreads();
    }
    if (threadIdx.x == 0) d_offs[NN] = carry;
}

// scatter CSR: srcp + permuted eattr rows in one pass
__global__ void scatter_kernel(const int* __restrict__ src, const int* __restrict__ dst,
                               const float* __restrict__ ea, int n) {
    int i = blockIdx.x * blockDim.x + threadIdx.x;
    if (i < n) {
        int pos = atomicAdd(&d_cnt[dst[i]], 1);
        d_srcp[pos] = src[i];
        const float4* s = (const float4*)(ea + (size_t)i * EIN);
        float4* d = (float4*)(d_eap + (size_t)pos * EIN);
        d[0] = s[0]; d[1] = s[1]; d[2] = s[2]; d[3] = s[3];
    }
}

__global__ void logdeg_sum_kernel() {
    __shared__ float sh[256];
    float s = 0.f;
    for (int i = blockIdx.x * blockDim.x + threadIdx.x; i < NN; i += gridDim.x * blockDim.x)
        s += log1pf((float)d_deg[i]);
    sh[threadIdx.x] = s;
    __syncthreads();
    for (int off = 128; off > 0; off >>= 1) {
        if (threadIdx.x < (unsigned)off) sh[threadIdx.x] += sh[threadIdx.x + off];
        __syncthreads();
    }
    if (threadIdx.x == 0) atomicAdd(&d_avg[0], sh[0]);
}

__global__ void scalers_kernel() {
    int i = blockIdx.x * blockDim.x + threadIdx.x;
    if (i < NN) {
        float avg  = d_avg[0] / (float)NN;
        float degc = fmaxf((float)d_deg[i], 1.f);
        float l    = logf(degc + 1.f);
        d_amp[i] = l / avg;
        d_att[i] = avg / l;
    }
}

// batched vecmat over blockIdx.x = layer; writes into arbitrary strided output
__global__ void vecmatb_kernel(const float* __restrict__ v, long sv,
                               const float* __restrict__ W, int ldw, long sw,
                               const float* __restrict__ badd, long sb,
                               float* __restrict__ out, long so) {
    int l = blockIdx.x, c = threadIdx.x;
    const float* vl = v + l * sv;
    const float* Wl = W + l * sw;
    float s = 0.f;
    for (int j = 0; j < HH; j++) s = fmaf(vl[j], Wl[j * ldw + c], s);
    out[l * so + c] = s + badd[l * sb + c];
}

// Wc [384,128] from preW (W0,W1) and Y rows 0..127 (Q0); batched over z
__global__ void wconv_kernel(const float* __restrict__ preW) {
    int l = blockIdx.z;
    int i = blockIdx.x * blockDim.x + threadIdx.x;   // 384*128
    if (i >= 384 * 128) return;
    int n = i >> 7, k = i & 127;
    float v;
    if (n < 256) {
        int c = n & 127;
        v = preW[(size_t)l * 3 * HH * HH + ((n >> 7) ? HH * HH : 0) + k * HH + c];
    } else {
        v = d_Y[(size_t)l * 13 * HH * HH + (size_t)k * HH + (n - 256)];
    }
    __nv_bfloat16 h, lo; split1(v, h, lo);
    size_t o = (size_t)l * 3 * HH * HH + (size_t)n * HH + k;
    d_Wch[o] = h; d_Wcl[o] = lo;
}

// Qc [384,512] from Y rows 128..1663 — coalesced via 32x32 smem transpose tile.
// blockIdx.z = l*3+q ; input Ain[k][c] = Y[128 + q*512 + k][c] -> Qc[(q*128+c)*512 + k].
__global__ void qconv_kernel() {
    __shared__ float tile[32][33];
    int l = blockIdx.z / 3, q = blockIdx.z % 3;
    int k0 = blockIdx.x * 32, c0 = blockIdx.y * 32;
    const float* Yl = d_Y + (size_t)l * 13 * HH * HH;
#pragma unroll
    for (int j = 0; j < 4; j++) {
        int k = k0 + threadIdx.y + j * 8;
        tile[threadIdx.y + j * 8][threadIdx.x] =
            Yl[(size_t)(128 + q * 512 + k) * HH + c0 + threadIdx.x];   // coalesced over c
    }
    __syncthreads();
#pragma unroll
    for (int j = 0; j < 4; j++) {
        int c = c0 + threadIdx.y + j * 8;
        float v = tile[threadIdx.x][threadIdx.y + j * 8];
        __nv_bfloat16 h, lo; split1(v, h, lo);
        size_t o = (size_t)l * 384 * 512 + (size_t)(q * 128 + c) * 512 + k0 + threadIdx.x;
        d_Qch[o] = h; d_Qcl[o] = lo;                                   // coalesced over k
    }
}

// per-edge message value for column c (16 FMAs against S registers)
__device__ __forceinline__ float edge_msg(int r, const float* Sreg, float base) {
    const float4* ea = (const float4*)(d_eap + (size_t)r * EIN);
    float4 e0 = ea[0], e1 = ea[1], e2 = ea[2], e3 = ea[3];
    float v = base;
    v = fmaf(e0.x, Sreg[0],  v); v = fmaf(e0.y, Sreg[1],  v);
    v = fmaf(e0.z, Sreg[2],  v); v = fmaf(e0.w, Sreg[3],  v);
    v = fmaf(e1.x, Sreg[4],  v); v = fmaf(e1.y, Sreg[5],  v);
    v = fmaf(e1.z, Sreg[6],  v); v = fmaf(e1.w, Sreg[7],  v);
    v = fmaf(e2.x, Sreg[8],  v); v = fmaf(e2.y, Sreg[9],  v);
    v = fmaf(e2.z, Sreg[10], v); v = fmaf(e2.w, Sreg[11], v);
    v = fmaf(e3.x, Sreg[12], v); v = fmaf(e3.y, Sreg[13], v);
    v = fmaf(e3.z, Sreg[14], v); v = fmaf(e3.w, Sreg[15], v);
    return v;
}

// segmented aggregation, grid-stride over nodes; 2-edge unroll (validated optimum).
__global__ void __launch_bounds__(128) agg_kernel(const float* __restrict__ S) {
    int c = threadIdx.x;
    float Sreg[16];
#pragma unroll
    for (int k = 0; k < 16; k++) Sreg[k] = S[k * HH + c];
    for (int node = blockIdx.x; node < NN; node += gridDim.x) {
        int s = d_offs[node], e = d_offs[node + 1];
        float hd = d_cmb[(size_t)node * 384 + c];
        float sum = 0.f, ss = 0.f, mn = INFINITY, mx = -INFINITY;
        int r = s;
        for (; r + 2 <= e; r += 2) {
            int sp0 = d_srcp[r], sp1 = d_srcp[r + 1];
            float hs0 = d_cmb[(size_t)sp0 * 384 + 128 + c];
            float hs1 = d_cmb[(size_t)sp1 * 384 + 128 + c];
            float v0 = edge_msg(r,     Sreg, hd + hs0);
            float v1 = edge_msg(r + 1, Sreg, hd + hs1);
            sum += v0; ss = fmaf(v0, v0, ss);
            mn = fminf(mn, v0); mx = fmaxf(mx, v0);
            sum += v1; ss = fmaf(v1, v1, ss);
            mn = fminf(mn, v1); mx = fmaxf(mx, v1);
        }
        if (r < e) {
            int sp = d_srcp[r];
            float v = edge_msg(r, Sreg, hd + d_cmb[(size_t)sp * 384 + 128 + c]);
            sum += v; ss = fmaf(v, v, ss);
            mn = fminf(mn, v); mx = fmaxf(mx, v);
        }
        float deg  = (float)(e - s);
        float degc = fmaxf(deg, 1.f);
        float mean = sum / degc;
        float var  = ss / degc - mean * mean;
        float sd   = sqrtf(fmaxf(var, 0.f) + 1e-5f);
        if (e == s) { mn = 0.f; mx = 0.f; }
        size_t o = (size_t)node * 512;
        __nv_bfloat16 h, l;
        split1(mean, h, l); d_agh[o +       c] = h; d_agl[o +       c] = l;
        split1(mn,   h, l); d_agh[o + 128 + c] = h; d_agl[o + 128 + c] = l;
        split1(mx,   h, l); d_agh[o + 256 + c] = h; d_agl[o + 256 + c] = l;
        split1(sd,   h, l); d_agh[o + 384 + c] = h; d_agl[o + 384 + c] = l;
    }
}

// h_next = relu(z(+b2) + y0 + amp*y1 + att*y2); writes bf16 splits only
__global__ void combine_kernel(__nv_bfloat16* __restrict__ hh, __nv_bfloat16* __restrict__ hl) {
    int i = blockIdx.x * blockDim.x + threadIdx.x;   // NN*32 threads, 4 cols each
    if (i >= NN * 32) return;
    int node = i >> 5, c = (i & 31) * 4;
    size_t co = (size_t)node * 384;
    float4 zv = *(const float4*)&d_cmb[co + 256 + c];
    float4 y0 = *(const float4*)&d_y[co + c];
    float4 y1 = *(const float4*)&d_y[co + 128 + c];
    float4 y2 = *(const float4*)&d_y[co + 256 + c];
    float amp = d_amp[node], att = d_att[node];
    float v0 = fmaxf(zv.x + y0.x + amp * y1.x + att * y2.x, 0.f);
    float v1 = fmaxf(zv.y + y0.y + amp * y1.y + att * y2.y, 0.f);
    float v2 = fmaxf(zv.z + y0.z + amp * y1.z + att * y2.z, 0.f);
    float v3 = fmaxf(zv.w + y0.w + amp * y1.w + att * y2.w, 0.f);
    __nv_bfloat16 h0, l0, h1, l1, h2, l2, h3, l3;
    split1(v0, h0, l0); split1(v1, h1, l1); split1(v2, h2, l2); split1(v3, h3, l3);
    __nv_bfloat162 hp0; hp0.x = h0; hp0.y = h1;
    __nv_bfloat162 hp1; hp1.x = h2; hp1.y = h3;
    __nv_bfloat162 lp0; lp0.x = l0; lp0.y = l1;
    __nv_bfloat162 lp1; lp1.x = l2; lp1.y = l3;
    size_t o = (size_t)node * HH + c;
    *(__nv_bfloat162*)&hh[o]     = hp0;
    *(__nv_bfloat162*)&hh[o + 2] = hp1;
    *(__nv_bfloat162*)&hl[o]     = lp0;
    *(__nv_bfloat162*)&hl[o + 2] = lp1;
}

// pool from bf16 splits (h = hi + lo)
__global__ void pool_kernel(const __nv_bfloat16* __restrict__ hh,
                            const __nv_bfloat16* __restrict__ hl,
                            const int* __restrict__ batch) {
    int i = blockIdx.x * blockDim.x + threadIdx.x;
    if (i >= NN * HH) return;
    int node = i >> 7, c = i & 127;
    float h = __bfloat162float(hh[i]) + __bfloat162float(hl[i]);
    atomicAdd(&d_g[batch[node] * HH + c], h);
}

__global__ void head_kernel(const float* __restrict__ W, const float* __restrict__ b,
                            float* __restrict__ out) {
    __shared__ float sh[HH];
    sh[threadIdx.x] = d_g[blockIdx.x * HH + threadIdx.x];
    __syncthreads();
    if (threadIdx.x < OUTC) {
        float s = b[threadIdx.x];
        for (int k = 0; k < HH; k++) s = fmaf(sh[k], W[k * OUTC + threadIdx.x], s);
        out[blockIdx.x * OUTC + threadIdx.x] = s;
    }
}

// ---------------- host orchestration ----------------
static void gemm_b(const float* A, int lda, long sA, const float* B, int ldb, long sB,
                   float* C, int ldc, long sC, int M, int N, int K) {
    dim3 grid(N / 128, (M + 127) / 128, LL);
    sgemm_batched_kernel<<<grid, 256>>>(A, lda, sA, B, ldb, sB, C, ldc, sC, M, N, K);
}

static void tgemm(const __nv_bfloat16* Ah, const __nv_bfloat16* Al,
                  const __nv_bfloat16* Bh, const __nv_bfloat16* Bl,
                  float* C, int ldc, int M, int N, int K, const float* bias) {
    dim3 grid((M + 127) / 128, N / 128);
    hmma_kernel<<<grid, 256, TSMEM>>>(Ah, Al, Bh, Bl, C, ldc, M, K, bias);
}

template <typename T>
static T* sym(const void* symbol) {
    void* p = nullptr;
    cudaGetSymbolAddress(&p, symbol);
    return (T*)p;
}

extern "C" void kernel_launch(void* const* d_in, const int* in_sizes, int n_in,
                              void* d_out, int out_size) {
    const float* x     = (const float*)d_in[0];
    const float* eattr = (const float*)d_in[1];
    const int*   src   = (const int*)  d_in[2];
    const int*   dst   = (const int*)  d_in[3];
    const int*   batch = (const int*)  d_in[4];
    const float* nW    = (const float*)d_in[5];
    const float* nb    = (const float*)d_in[6];
    const float* eW    = (const float*)d_in[7];
    const float* eb    = (const float*)d_in[8];
    const float* encW  = (const float*)d_in[9];
    const float* encb  = (const float*)d_in[10];
    const float* preW  = (const float*)d_in[11];
    const float* preb  = (const float*)d_in[12];
    const float* postW = (const float*)d_in[13];
    const float* postb = (const float*)d_in[14];
    const float* linW  = (const float*)d_in[15];
    const float* linb  = (const float*)d_in[16];
    const float* headW = (const float*)d_in[17];
    const float* headb = (const float*)d_in[18];
    float* out = (float*)d_out;

    float* cmb  = sym<float>(d_cmb);
    __nv_bfloat16* agh = sym<__nv_bfloat16>(d_agh);
    __nv_bfloat16* agl = sym<__nv_bfloat16>(d_agl);
    float* y    = sym<float>(d_y);
    __nv_bfloat16* hh[2] = { sym<__nv_bfloat16>(d_hh0), sym<__nv_bfloat16>(d_hh1) };
    __nv_bfloat16* hl[2] = { sym<__nv_bfloat16>(d_hl0), sym<__nv_bfloat16>(d_hl1) };
    int*   deg  = sym<int>(d_deg);
    int*   offs = sym<int>(d_offs);
    int*   cnt  = sym<int>(d_cnt);
    float* avg  = sym<float>(d_avg);
    float* S    = sym<float>(d_S);
    float* T1   = sym<float>(d_T1);
    float* uv   = sym<float>(d_uv);
    float* Yb   = sym<float>(d_Y);
    float* cbias= sym<float>(d_cbias);
    float* g    = sym<float>(d_g);
    __nv_bfloat16* Wch = sym<__nv_bfloat16>(d_Wch); __nv_bfloat16* Wcl = sym<__nv_bfloat16>(d_Wcl);
    __nv_bfloat16* Qch = sym<__nv_bfloat16>(d_Qch); __nv_bfloat16* Qcl = sym<__nv_bfloat16>(d_Qcl);

    cudaFuncSetAttribute(hmma_kernel, cudaFuncAttributeMaxDynamicSharedMemorySize, TSMEM);

    const int TPB = 256;

    // ---- graph structure ----
    cudaMemsetAsync(deg, 0, NN * sizeof(int), 0);
    cudaMemsetAsync(avg, 0, sizeof(float), 0);
    cudaMemsetAsync(cbias, 0, LL * 3 * HH * sizeof(float), 0);
    count_kernel<<<(EE + TPB - 1) / TPB, TPB>>>(dst, EE);
    scan_kernel<<<1, 1024>>>();
    cudaMemcpyAsync(cnt, offs, NN * sizeof(int), cudaMemcpyDeviceToDevice, 0);
    scatter_kernel<<<(EE + TPB - 1) / TPB, TPB>>>(src, dst, eattr, EE);
    logdeg_sum_kernel<<<256, 256>>>();
    scalers_kernel<<<(NN + TPB - 1) / TPB, TPB>>>();

    // ---- node embedding: GEMM straight into bf16 splits ----
    {
        dim3 grid(HH / 128, (NN + 127) / 128);
        sgemm_split_kernel<<<grid, 256>>>(x, FIN, nW, HH, NN, HH, FIN, nb, hh[0], hl[0]);
    }

    // ---- batched per-layer weight precompute ----
    gemm_b(eW, HH, 0, encW, HH, (long)HH * HH, T1, HH, (long)EIN * HH, EIN, HH, HH);
    gemm_b(T1, HH, (long)EIN * HH, preW + 2 * HH * HH, HH, (long)3 * HH * HH,
           S, HH, (long)EIN * HH, EIN, HH, HH);
    gemm_b(postW, HH, (long)13 * HH * HH, linW, HH, (long)HH * HH,
           Yb, HH, (long)13 * HH * HH, 13 * HH, HH, HH);
    vecmatb_kernel<<<LL, HH>>>(eb, 0, encW, HH, (long)HH * HH, encb, HH, uv, HH);
    vecmatb_kernel<<<LL, HH>>>(uv, HH, preW + 2 * HH * HH, HH, (long)3 * HH * HH,
                               preb, HH, cbias, 3 * HH);
    vecmatb_kernel<<<LL, HH>>>(postb, HH, linW, HH, (long)HH * HH,
                               linb, HH, cbias + 256, 3 * HH);
    {
        dim3 gw((384 * 128 + TPB - 1) / TPB, 1, LL);
        wconv_kernel<<<gw, TPB>>>(preW);
        dim3 gq(512 / 32, 128 / 32, LL * 3);
        qconv_kernel<<<gq, dim3(32, 8)>>>();
    }

    // ---- layers ----
    int cb = 0;
    for (int l = 0; l < LL; l++) {
        // cmb = h @ [W0 | W1 | Q0] + [tl|0|b2]  -> [hd+tl | hs | z+b2], N=384
        tgemm(hh[cb], hl[cb], Wch + (size_t)l * 3 * HH * HH, Wcl + (size_t)l * 3 * HH * HH,
              cmb, 3 * HH, NN, 3 * HH, HH, cbias + l * 3 * HH);
        // segmented aggregation with fused rank-16 edge message -> agg splits [N,512]
        agg_kernel<<<4096, 128>>>(S + (size_t)l * EIN * HH);
        // y = agg @ Qcat_l  [N,384]
        tgemm(agh, agl, Qch + (size_t)l * 384 * 512, Qcl + (size_t)l * 384 * 512,
              y, 3 * HH, NN, 3 * HH, 4 * HH, nullptr);
        // combine -> splits only
        combine_kernel<<<(NN * 32 + TPB - 1) / TPB, TPB>>>(hh[cb ^ 1], hl[cb ^ 1]);
        cb ^= 1;
    }

    // ---- pool + head ----
    cudaMemsetAsync(g, 0, GG * HH * sizeof(float), 0);
    pool_kernel<<<(NN * HH + TPB - 1) / TPB, TPB>>>(hh[cb], hl[cb], batch);
    head_kernel<<<GG, HH>>>(headW, headb, out);
}

// round 17
// speedup vs baseline: 1.0765x; 1.0193x over previous
#include <cuda_runtime.h>
#include <math.h>
#include <stdint.h>
#include <cuda_bf16.h>

// ---------------- problem constants ----------------
static const int NN   = 50000;   // nodes
static const int EE   = 400000;  // edges
static const int FIN  = 64;
static const int EIN  = 16;
static const int HH   = 128;
static const int LL   = 4;
static const int GG   = 256;
static const int OUTC = 12;

// ---------------- scratch (static device globals; no runtime alloc) ----------------
__device__ float d_eap[(size_t)EE * EIN];       // permuted raw edge attrs (CSR order)
__device__ float d_cmb[(size_t)NN * 3 * HH];    // [hd+tl | hs | z+b2] per node
__device__ __nv_bfloat16 d_agh[(size_t)NN * 4 * HH];
__device__ __nv_bfloat16 d_agl[(size_t)NN * 4 * HH];
__device__ float d_y  [(size_t)NN * 3 * HH];    // agg @ Qcat
__device__ __nv_bfloat16 d_hh0[(size_t)NN * HH];
__device__ __nv_bfloat16 d_hl0[(size_t)NN * HH];
__device__ __nv_bfloat16 d_hh1[(size_t)NN * HH];
__device__ __nv_bfloat16 d_hl1[(size_t)NN * HH];
__device__ int   d_deg [NN];
__device__ int   d_offs[NN + 1];
__device__ int   d_cnt [NN];
__device__ int   d_srcp[EE];
__device__ float d_amp[NN];
__device__ float d_att[NN];
__device__ float d_avg[1];
__device__ float d_S   [LL * EIN * HH];         // eW@Wenc@Wpre2 per layer [16,128]
__device__ float d_T1  [LL * EIN * HH];         // temp (batched)
__device__ float d_uv  [LL * HH];               // temp (batched)
__device__ float d_Y   [(size_t)LL * 13 * HH * HH]; // [P0|P1..P12]@lin per layer [1664,128]
__device__ float d_cbias[LL * 3 * HH];          // [tl | 0 | b2] per layer
__device__ float d_g   [GG * HH];
// transposed bf16-split weights (Bt layout: [N,K] row-major)
__device__ __nv_bfloat16 d_Wch[LL * 3 * HH * HH], d_Wcl[LL * 3 * HH * HH];   // [384,128]: W0|W1|Q0
__device__ __nv_bfloat16 d_Qch[LL * 3 * HH * 4 * HH], d_Qcl[LL * 3 * HH * 4 * HH]; // [384,512]

// ================= common MMA helpers =================
static const int HPAD = 40;                 // padded K-stride in bf16 (conflict-free ldmatrix)

#define LDSM4(R, ADDR) \
    asm volatile("ldmatrix.sync.aligned.m8n8.x4.shared.b16 {%0,%1,%2,%3}, [%4];" \
        : "=r"((R)[0]), "=r"((R)[1]), "=r"((R)[2]), "=r"((R)[3]) : "r"(ADDR))

#define MMA16816(D, A, B) \
    asm volatile("mma.sync.aligned.m16n8k16.row.col.f32.bf16.bf16.f32 " \
        "{%0,%1,%2,%3}, {%4,%5,%6,%7}, {%8,%9}, {%0,%1,%2,%3};" \
        : "+f"((D)[0]), "+f"((D)[1]), "+f"((D)[2]), "+f"((D)[3]) \
        : "r"((A)[0]), "r"((A)[1]), "r"((A)[2]), "r"((A)[3]), "r"((B)[0]), "r"((B)[1]))

__device__ __forceinline__ uint32_t smem_u32(const void* p) {
    uint32_t a;
    asm("{ .reg .u64 t; cvta.to.shared.u64 t, %1; cvt.u32.u64 %0, t; }" : "=r"(a) : "l"(p));
    return a;
}

__device__ __forceinline__ void split1(float x, __nv_bfloat16& h, __nv_bfloat16& l) {
    h = __float2bfloat16(x);
    l = __float2bfloat16(x - __bfloat162float(h));
}

// ================= bf16x3 GEMM (mma.sync, 128x128 tile, 2 CTA/SM) =================
// Single barrier per K-chunk: wait -> barrier -> compute(ks=0) -> issue(ch+1) -> compute(ks=1).
static const int TILEB = 128 * HPAD * 2;    // 10240 B per tile
static const int BUFB  = 4 * TILEB;         // Ah,Al,Bh,Bl
static const int TSMEM = 2 * BUFB;          // 81920 B

__global__ void __launch_bounds__(256, 2) hmma_kernel(
    const __nv_bfloat16* __restrict__ Ah, const __nv_bfloat16* __restrict__ Al,
    const __nv_bfloat16* __restrict__ Bh, const __nv_bfloat16* __restrict__ Bl,
    float* __restrict__ C, int ldc, int M, int K,
    const float* __restrict__ bias)
{
    extern __shared__ char smem[];
    const uint32_t sb = smem_u32(smem);
    const int tid = threadIdx.x, lane = tid & 31, wid = tid >> 5;
    const int warp_m = wid & 3, warp_n = wid >> 2;         // 4 x 2 warps
    const int m0 = blockIdx.x * 128, n0 = blockIdx.y * 128;

    const int OAH = 0, OAL = TILEB, OBH = 2 * TILEB, OBL = 3 * TILEB;

    float acc[2][8][4];
#pragma unroll
    for (int i = 0; i < 2; i++)
#pragma unroll
        for (int j = 0; j < 8; j++)
#pragma unroll
            for (int k = 0; k < 4; k++) acc[i][j][k] = 0.f;

    const int ldr = tid >> 2;
    const int ldc8 = (tid & 3) * 8;
    auto issue_chunk = [&](int buf, int k0) {
        uint32_t bo = sb + buf * BUFB;
#pragma unroll
        for (int half = 0; half < 2; half++) {
            int r = half * 64 + ldr;
            uint32_t soff = (uint32_t)(r * HPAD + ldc8) * 2;
            int arow = m0 + r;
            int asz = (arow < M) ? 16 : 0;
            const void* gah = Ah + (size_t)arow * K + k0 + ldc8;
            const void* gal = Al + (size_t)arow * K + k0 + ldc8;
            asm volatile("cp.async.cg.shared.global [%0], [%1], 16, %2;"
                         :: "r"(bo + OAH + soff), "l"(gah), "r"(asz));
            asm volatile("cp.async.cg.shared.global [%0], [%1], 16, %2;"
                         :: "r"(bo + OAL + soff), "l"(gal), "r"(asz));
            const void* gbh = Bh + (size_t)(n0 + r) * K + k0 + ldc8;
            const void* gbl = Bl + (size_t)(n0 + r) * K + k0 + ldc8;
            asm volatile("cp.async.cg.shared.global [%0], [%1], 16;"
                         :: "r"(bo + OBH + soff), "l"(gbh));
            asm volatile("cp.async.cg.shared.global [%0], [%1], 16;"
                         :: "r"(bo + OBL + soff), "l"(gbl));
        }
        asm volatile("cp.async.commit_group;");
    };

    const int a_r  = lane & 15;
    const int a_kg = (lane >> 4) * 8;
    const int b_r  = (lane & 7) + ((lane >> 4) * 8);
    const int b_kg = ((lane >> 3) & 1) * 8;

    const int nchunks = K >> 5;
    issue_chunk(0, 0);

    for (int ch = 0; ch < nchunks; ch++) {
        asm volatile("cp.async.wait_group 0;");
        __syncthreads();

        uint32_t bo = sb + (ch & 1) * BUFB;
#pragma unroll
        for (int ks = 0; ks < 2; ks++) {
            int kc = ks * 16;
            uint32_t afh[2][4], afl[2][4];
#pragma unroll
            for (int mt = 0; mt < 2; mt++) {
                int row = warp_m * 32 + mt * 16 + a_r;
                uint32_t ad = bo + (uint32_t)(row * HPAD + kc + a_kg) * 2;
                LDSM4(afh[mt], ad + OAH);
                LDSM4(afl[mt], ad + OAL);
            }
#pragma unroll
            for (int np = 0; np < 4; np++) {
                uint32_t bfh[4], bfl[4];
                int nrow = warp_n * 64 + np * 16 + b_r;
                uint32_t bd = bo + (uint32_t)(nrow * HPAD + kc + b_kg) * 2;
                LDSM4(bfh, bd + OBH);
                LDSM4(bfl, bd + OBL);
#pragma unroll
                for (int mt = 0; mt < 2; mt++) {
                    MMA16816(acc[mt][np * 2 + 0], afh[mt], (&bfh[0]));
                    MMA16816(acc[mt][np * 2 + 1], afh[mt], (&bfh[2]));
                    MMA16816(acc[mt][np * 2 + 0], afl[mt], (&bfh[0]));
                    MMA16816(acc[mt][np * 2 + 1], afl[mt], (&bfh[2]));
                    MMA16816(acc[mt][np * 2 + 0], afh[mt], (&bfl[0]));
                    MMA16816(acc[mt][np * 2 + 1], afh[mt], (&bfl[2]));
                }
            }
            if (ks == 0 && ch + 1 < nchunks) issue_chunk((ch + 1) & 1, (ch + 1) << 5);
        }
    }

    const int mrow = m0 + warp_m * 32;
    const int ncol = n0 + warp_n * 64;
#pragma unroll
    for (int mt = 0; mt < 2; mt++) {
#pragma unroll
        for (int nt = 0; nt < 8; nt++) {
            int c = ncol + nt * 8 + (lane & 3) * 2;
            float2 bv = bias ? *(const float2*)&bias[c] : make_float2(0.f, 0.f);
            int r0 = mrow + mt * 16 + (lane >> 2);
            if (r0 < M) {
                float2 v = make_float2(acc[mt][nt][0] + bv.x, acc[mt][nt][1] + bv.y);
                *(float2*)&C[(size_t)r0 * ldc + c] = v;
            }
            int r1 = r0 + 8;
            if (r1 < M) {
                float2 v = make_float2(acc[mt][nt][2] + bv.x, acc[mt][nt][3] + bv.y);
                *(float2*)&C[(size_t)r1 * ldc + c] = v;
            }
        }
    }
}

// ---------------- fp32 SGEMM (batched fp32-out / split-out) ----------------
template <int MODE>   // 0 = fp32 C, 1 = bf16 hi/lo split output
__device__ __forceinline__ void sgemm_body(
    const float* A, int lda, const float* B, int ldb, float* C, int ldc,
    int M, int N, int K, const float* bias,
    __nv_bfloat16* Hi, __nv_bfloat16* Lo)
{
    const int BM = 128, BN = 128, BK = 8;
    __shared__ float As[BK][BM];
    __shared__ float Bs[BK][BN];
    int tid = threadIdx.x;
    int brow = blockIdx.y, bcol = blockIdx.x;
    int aRow = tid >> 1, aCol4 = (tid & 1) * 4;
    int bRow = tid >> 5, bCol4 = (tid & 31) * 4;
    int tr = (tid >> 4) * 8, tc = (tid & 15) * 8;
    float acc[8][8];
#pragma unroll
    for (int i = 0; i < 8; i++)
#pragma unroll
        for (int j = 0; j < 8; j++) acc[i][j] = 0.f;
    int gArow = brow * BM + aRow;
    bool aValid = gArow < M;
    const float* Aptr = A + (long)(aValid ? gArow : 0) * lda + aCol4;
    const float* Bptr = B + (long)bRow * ldb + (long)bcol * BN + bCol4;
    for (int k0 = 0; k0 < K; k0 += BK) {
        float4 av = aValid ? *(const float4*)(Aptr + k0) : make_float4(0.f, 0.f, 0.f, 0.f);
        float4 bv = *(const float4*)(Bptr + (long)k0 * ldb);
        As[aCol4 + 0][aRow] = av.x; As[aCol4 + 1][aRow] = av.y;
        As[aCol4 + 2][aRow] = av.z; As[aCol4 + 3][aRow] = av.w;
        *(float4*)&Bs[bRow][bCol4] = bv;
        __syncthreads();
#pragma unroll
        for (int kk = 0; kk < BK; kk++) {
            float ar[8], br[8];
#pragma unroll
            for (int i = 0; i < 8; i++) ar[i] = As[kk][tr + i];
#pragma unroll
            for (int j = 0; j < 8; j++) br[j] = Bs[kk][tc + j];
#pragma unroll
            for (int i = 0; i < 8; i++)
#pragma unroll
                for (int j = 0; j < 8; j++)
                    acc[i][j] = fmaf(ar[i], br[j], acc[i][j]);
        }
        __syncthreads();
    }
#pragma unroll
    for (int i = 0; i < 8; i++) {
        int row = brow * BM + tr + i;
        if (row < M) {
#pragma unroll
            for (int j = 0; j < 8; j += 4) {
                int col = bcol * BN + tc + j;
                float4 v;
                v.x = acc[i][j + 0] + (bias ? bias[col + 0] : 0.f);
                v.y = acc[i][j + 1] + (bias ? bias[col + 1] : 0.f);
                v.z = acc[i][j + 2] + (bias ? bias[col + 2] : 0.f);
                v.w = acc[i][j + 3] + (bias ? bias[col + 3] : 0.f);
                if (MODE == 0) {
                    *(float4*)&C[(long)row * ldc + col] = v;
                } else {
                    __nv_bfloat16 h0, l0, h1, l1, h2, l2, h3, l3;
                    split1(v.x, h0, l0); split1(v.y, h1, l1);
                    split1(v.z, h2, l2); split1(v.w, h3, l3);
                    __nv_bfloat162 hp0; hp0.x = h0; hp0.y = h1;
                    __nv_bfloat162 hp1; hp1.x = h2; hp1.y = h3;
                    __nv_bfloat162 lp0; lp0.x = l0; lp0.y = l1;
                    __nv_bfloat162 lp1; lp1.x = l2; lp1.y = l3;
                    long o = (long)row * ldc + col;
                    *(__nv_bfloat162*)&Hi[o]     = hp0;
                    *(__nv_bfloat162*)&Hi[o + 2] = hp1;
                    *(__nv_bfloat162*)&Lo[o]     = lp0;
                    *(__nv_bfloat162*)&Lo[o + 2] = lp1;
                }
            }
        }
    }
}

__global__ void __launch_bounds__(256) sgemm_split_kernel(
    const float* __restrict__ A, int lda,
    const float* __restrict__ B, int ldb,
    int M, int N, int K, const float* __restrict__ bias,
    __nv_bfloat16* __restrict__ Hi, __nv_bfloat16* __restrict__ Lo)
{
    sgemm_body<1>(A, lda, B, ldb, nullptr, N, M, N, K, bias, Hi, Lo);
}

__global__ void __launch_bounds__(256) sgemm_batched_kernel(
    const float* __restrict__ A, int lda, long strideA,
    const float* __restrict__ B, int ldb, long strideB,
    float* __restrict__ C, int ldc, long strideC,
    int M, int N, int K)
{
    int l = blockIdx.z;
    sgemm_body<0>(A + (long)l * strideA, lda, B + (long)l * strideB, ldb,
                  C + (long)l * strideC, ldc, M, N, K, nullptr, nullptr, nullptr);
}

// ---------------- small helper kernels ----------------
__global__ void count_kernel(const int* __restrict__ dst, int n) {
    int i = blockIdx.x * blockDim.x + threadIdx.x;
    if (i < n) atomicAdd(&d_deg[dst[i]], 1);
}

// single-block exclusive scan, warp-shfl hierarchy: 4 barriers per 1024-chunk
__global__ void scan_kernel() {
    __shared__ int warp_sums[32];
    __shared__ int carry_sh;
    const int lane = threadIdx.x & 31, wid = threadIdx.x >> 5;   // 32 warps
    if (threadIdx.x == 0) carry_sh = 0;
    __syncthreads();
    for (int base = 0; base < NN; base += 1024) {
        int i = base + (int)threadIdx.x;
        int v = (i < NN) ? d_deg[i] : 0;
        // inclusive warp scan via shfl (no barriers)
        int x = v;
#pragma unroll
        for (int off = 1; off < 32; off <<= 1) {
            int t = __shfl_up_sync(0xFFFFFFFFu, x, off);
            if (lane >= off) x += t;
        }
        if (lane == 31) warp_sums[wid] = x;
        __syncthreads();
        if (wid == 0) {
            int ws = warp_sums[lane];
#pragma unroll
            for (int off = 1; off < 32; off <<= 1) {
                int t = __shfl_up_sync(0xFFFFFFFFu, ws, off);
                if (lane >= off) ws += t;
            }
            warp_sums[lane] = ws;
        }
        __syncthreads();
        int warp_off = (wid > 0) ? warp_sums[wid - 1] : 0;
        int carry = carry_sh;
        if (i < NN) d_offs[i] = carry + warp_off + x - v;   // exclusive
        __syncthreads();                                    // all reads of carry_sh done
        if (threadIdx.x == 0) carry_sh += warp_sums[31];    // chunk total
        __syncthreads();
    }
    if (threadIdx.x == 0) d_offs[NN] = carry_sh;
}

// scatter CSR: srcp + permuted eattr rows in one pass
__global__ void scatter_kernel(const int* __restrict__ src, const int* __restrict__ dst,
                               const float* __restrict__ ea, int n) {
    int i = blockIdx.x * blockDim.x + threadIdx.x;
    if (i < n) {
        int pos = atomicAdd(&d_cnt[dst[i]], 1);
        d_srcp[pos] = src[i];
        const float4* s = (const float4*)(ea + (size_t)i * EIN);
        float4* d = (float4*)(d_eap + (size_t)pos * EIN);
        d[0] = s[0]; d[1] = s[1]; d[2] = s[2]; d[3] = s[3];
    }
}

__global__ void logdeg_sum_kernel() {
    __shared__ float sh[256];
    float s = 0.f;
    for (int i = blockIdx.x * blockDim.x + threadIdx.x; i < NN; i += gridDim.x * blockDim.x)
        s += log1pf((float)d_deg[i]);
    sh[threadIdx.x] = s;
    __syncthreads();
    for (int off = 128; off > 0; off >>= 1) {
        if (threadIdx.x < (unsigned)off) sh[threadIdx.x] += sh[threadIdx.x + off];
        __syncthreads();
    }
    if (threadIdx.x == 0) atomicAdd(&d_avg[0], sh[0]);
}

__global__ void scalers_kernel() {
    int i = blockIdx.x * blockDim.x + threadIdx.x;
    if (i < NN) {
        float avg  = d_avg[0] / (float)NN;
        float degc = fmaxf((float)d_deg[i], 1.f);
        float l    = logf(degc + 1.f);
        d_amp[i] = l / avg;
        d_att[i] = avg / l;
    }
}

// batched vecmat over blockIdx.x = layer; writes into arbitrary strided output
__global__ void vecmatb_kernel(const float* __restrict__ v, long sv,
                               const float* __restrict__ W, int ldw, long sw,
                               const float* __restrict__ badd, long sb,
                               float* __restrict__ out, long so) {
    int l = blockIdx.x, c = threadIdx.x;
    const float* vl = v + l * sv;
    const float* Wl = W + l * sw;
    float s = 0.f;
    for (int j = 0; j < HH; j++) s = fmaf(vl[j], Wl[j * ldw + c], s);
    out[l * so + c] = s + badd[l * sb + c];
}

// Wc [384,128] from preW (W0,W1) and Y rows 0..127 (Q0); batched over z
__global__ void wconv_kernel(const float* __restrict__ preW) {
    int l = blockIdx.z;
    int i = blockIdx.x * blockDim.x + threadIdx.x;   // 384*128
    if (i >= 384 * 128) return;
    int n = i >> 7, k = i & 127;
    float v;
    if (n < 256) {
        int c = n & 127;
        v = preW[(size_t)l * 3 * HH * HH + ((n >> 7) ? HH * HH : 0) + k * HH + c];
    } else {
        v = d_Y[(size_t)l * 13 * HH * HH + (size_t)k * HH + (n - 256)];
    }
    __nv_bfloat16 h, lo; split1(v, h, lo);
    size_t o = (size_t)l * 3 * HH * HH + (size_t)n * HH + k;
    d_Wch[o] = h; d_Wcl[o] = lo;
}

// Qc [384,512] from Y rows 128..1663 — coalesced via 32x32 smem transpose tile.
__global__ void qconv_kernel() {
    __shared__ float tile[32][33];
    int l = blockIdx.z / 3, q = blockIdx.z % 3;
    int k0 = blockIdx.x * 32, c0 = blockIdx.y * 32;
    const float* Yl = d_Y + (size_t)l * 13 * HH * HH;
#pragma unroll
    for (int j = 0; j < 4; j++) {
        int k = k0 + threadIdx.y + j * 8;
        tile[threadIdx.y + j * 8][threadIdx.x] =
            Yl[(size_t)(128 + q * 512 + k) * HH + c0 + threadIdx.x];
    }
    __syncthreads();
#pragma unroll
    for (int j = 0; j < 4; j++) {
        int c = c0 + threadIdx.y + j * 8;
        float v = tile[threadIdx.x][threadIdx.y + j * 8];
        __nv_bfloat16 h, lo; split1(v, h, lo);
        size_t o = (size_t)l * 384 * 512 + (size_t)(q * 128 + c) * 512 + k0 + threadIdx.x;
        d_Qch[o] = h; d_Qcl[o] = lo;
    }
}

// per-edge message value for column c (16 FMAs against S registers)
__device__ __forceinline__ float edge_msg(int r, const float* Sreg, float base) {
    const float4* ea = (const float4*)(d_eap + (size_t)r * EIN);
    float4 e0 = ea[0], e1 = ea[1], e2 = ea[2], e3 = ea[3];
    float v = base;
    v = fmaf(e0.x, Sreg[0],  v); v = fmaf(e0.y, Sreg[1],  v);
    v = fmaf(e0.z, Sreg[2],  v); v = fmaf(e0.w, Sreg[3],  v);
    v = fmaf(e1.x, Sreg[4],  v); v = fmaf(e1.y, Sreg[5],  v);
    v = fmaf(e1.z, Sreg[6],  v); v = fmaf(e1.w, Sreg[7],  v);
    v = fmaf(e2.x, Sreg[8],  v); v = fmaf(e2.y, Sreg[9],  v);
    v = fmaf(e2.z, Sreg[10], v); v = fmaf(e2.w, Sreg[11], v);
    v = fmaf(e3.x, Sreg[12], v); v = fmaf(e3.y, Sreg[13], v);
    v = fmaf(e3.z, Sreg[14], v); v = fmaf(e3.w, Sreg[15], v);
    return v;
}

// segmented aggregation, grid-stride over nodes; 2-edge unroll (validated optimum).
__global__ void __launch_bounds__(128) agg_kernel(const float* __restrict__ S) {
    int c = threadIdx.x;
    float Sreg[16];
#pragma unroll
    for (int k = 0; k < 16; k++) Sreg[k] = S[k * HH + c];
    for (int node = blockIdx.x; node < NN; node += gridDim.x) {
        int s = d_offs[node], e = d_offs[node + 1];
        float hd = d_cmb[(size_t)node * 384 + c];
        float sum = 0.f, ss = 0.f, mn = INFINITY, mx = -INFINITY;
        int r = s;
        for (; r + 2 <= e; r += 2) {
            int sp0 = d_srcp[r], sp1 = d_srcp[r + 1];
            float hs0 = d_cmb[(size_t)sp0 * 384 + 128 + c];
            float hs1 = d_cmb[(size_t)sp1 * 384 + 128 + c];
            float v0 = edge_msg(r,     Sreg, hd + hs0);
            float v1 = edge_msg(r + 1, Sreg, hd + hs1);
            sum += v0; ss = fmaf(v0, v0, ss);
            mn = fminf(mn, v0); mx = fmaxf(mx, v0);
            sum += v1; ss = fmaf(v1, v1, ss);
            mn = fminf(mn, v1); mx = fmaxf(mx, v1);
        }
        if (r < e) {
            int sp = d_srcp[r];
            float v = edge_msg(r, Sreg, hd + d_cmb[(size_t)sp * 384 + 128 + c]);
            sum += v; ss = fmaf(v, v, ss);
            mn = fminf(mn, v); mx = fmaxf(mx, v);
        }
        float deg  = (float)(e - s);
        float degc = fmaxf(deg, 1.f);
        float mean = sum / degc;
        float var  = ss / degc - mean * mean;
        float sd   = sqrtf(fmaxf(var, 0.f) + 1e-5f);
        if (e == s) { mn = 0.f; mx = 0.f; }
        size_t o = (size_t)node * 512;
        __nv_bfloat16 h, l;
        split1(mean, h, l); d_agh[o +       c] = h; d_agl[o +       c] = l;
        split1(mn,   h, l); d_agh[o + 128 + c] = h; d_agl[o + 128 + c] = l;
        split1(mx,   h, l); d_agh[o + 256 + c] = h; d_agl[o + 256 + c] = l;
        split1(sd,   h, l); d_agh[o + 384 + c] = h; d_agl[o + 384 + c] = l;
    }
}

// h_next = relu(z(+b2) + y0 + amp*y1 + att*y2); writes bf16 splits only
__global__ void combine_kernel(__nv_bfloat16* __restrict__ hh, __nv_bfloat16* __restrict__ hl) {
    int i = blockIdx.x * blockDim.x + threadIdx.x;   // NN*32 threads, 4 cols each
    if (i >= NN * 32) return;
    int node = i >> 5, c = (i & 31) * 4;
    size_t co = (size_t)node * 384;
    float4 zv = *(const float4*)&d_cmb[co + 256 + c];
    float4 y0 = *(const float4*)&d_y[co + c];
    float4 y1 = *(const float4*)&d_y[co + 128 + c];
    float4 y2 = *(const float4*)&d_y[co + 256 + c];
    float amp = d_amp[node], att = d_att[node];
    float v0 = fmaxf(zv.x + y0.x + amp * y1.x + att * y2.x, 0.f);
    float v1 = fmaxf(zv.y + y0.y + amp * y1.y + att * y2.y, 0.f);
    float v2 = fmaxf(zv.z + y0.z + amp * y1.z + att * y2.z, 0.f);
    float v3 = fmaxf(zv.w + y0.w + amp * y1.w + att * y2.w, 0.f);
    __nv_bfloat16 h0, l0, h1, l1, h2, l2, h3, l3;
    split1(v0, h0, l0); split1(v1, h1, l1); split1(v2, h2, l2); split1(v3, h3, l3);
    __nv_bfloat162 hp0; hp0.x = h0; hp0.y = h1;
    __nv_bfloat162 hp1; hp1.x = h2; hp1.y = h3;
    __nv_bfloat162 lp0; lp0.x = l0; lp0.y = l1;
    __nv_bfloat162 lp1; lp1.x = l2; lp1.y = l3;
    size_t o = (size_t)node * HH + c;
    *(__nv_bfloat162*)&hh[o]     = hp0;
    *(__nv_bfloat162*)&hh[o + 2] = hp1;
    *(__nv_bfloat162*)&hl[o]     = lp0;
    *(__nv_bfloat162*)&hl[o + 2] = lp1;
}

// pool from bf16 splits (h = hi + lo)
__global__ void pool_kernel(const __nv_bfloat16* __restrict__ hh,
                            const __nv_bfloat16* __restrict__ hl,
                            const int* __restrict__ batch) {
    int i = blockIdx.x * blockDim.x + threadIdx.x;
    if (i >= NN * HH) return;
    int node = i >> 7, c = i & 127;
    float h = __bfloat162float(hh[i]) + __bfloat162float(hl[i]);
    atomicAdd(&d_g[batch[node] * HH + c], h);
}

__global__ void head_kernel(const float* __restrict__ W, const float* __restrict__ b,
                            float* __restrict__ out) {
    __shared__ float sh[HH];
    sh[threadIdx.x] = d_g[blockIdx.x * HH + threadIdx.x];
    __syncthreads();
    if (threadIdx.x < OUTC) {
        float s = b[threadIdx.x];
        for (int k = 0; k < HH; k++) s = fmaf(sh[k], W[k * OUTC + threadIdx.x], s);
        out[blockIdx.x * OUTC + threadIdx.x] = s;
    }
}

// ---------------- host orchestration ----------------
static void gemm_b(const float* A, int lda, long sA, const float* B, int ldb, long sB,
                   float* C, int ldc, long sC, int M, int N, int K) {
    dim3 grid(N / 128, (M + 127) / 128, LL);
    sgemm_batched_kernel<<<grid, 256>>>(A, lda, sA, B, ldb, sB, C, ldc, sC, M, N, K);
}

static void tgemm(const __nv_bfloat16* Ah, const __nv_bfloat16* Al,
                  const __nv_bfloat16* Bh, const __nv_bfloat16* Bl,
                  float* C, int ldc, int M, int N, int K, const float* bias) {
    dim3 grid((M + 127) / 128, N / 128);
    hmma_kernel<<<grid, 256, TSMEM>>>(Ah, Al, Bh, Bl, C, ldc, M, K, bias);
}

template <typename T>
static T* sym(const void* symbol) {
    void* p = nullptr;
    cudaGetSymbolAddress(&p, symbol);
    return (T*)p;
}

extern "C" void kernel_launch(void* const* d_in, const int* in_sizes, int n_in,
                              void* d_out, int out_size) {
    const float* x     = (const float*)d_in[0];
    const float* eattr = (const float*)d_in[1];
    const int*   src   = (const int*)  d_in[2];
    const int*   dst   = (const int*)  d_in[3];
    const int*   batch = (const int*)  d_in[4];
    const float* nW    = (const float*)d_in[5];
    const float* nb    = (const float*)d_in[6];
    const float* eW    = (const float*)d_in[7];
    const float* eb    = (const float*)d_in[8];
    const float* encW  = (const float*)d_in[9];
    const float* encb  = (const float*)d_in[10];
    const float* preW  = (const float*)d_in[11];
    const float* preb  = (const float*)d_in[12];
    const float* postW = (const float*)d_in[13];
    const float* postb = (const float*)d_in[14];
    const float* linW  = (const float*)d_in[15];
    const float* linb  = (const float*)d_in[16];
    const float* headW = (const float*)d_in[17];
    const float* headb = (const float*)d_in[18];
    float* out = (float*)d_out;

    float* cmb  = sym<float>(d_cmb);
    __nv_bfloat16* agh = sym<__nv_bfloat16>(d_agh);
    __nv_bfloat16* agl = sym<__nv_bfloat16>(d_agl);
    float* y    = sym<float>(d_y);
    __nv_bfloat16* hh[2] = { sym<__nv_bfloat16>(d_hh0), sym<__nv_bfloat16>(d_hh1) };
    __nv_bfloat16* hl[2] = { sym<__nv_bfloat16>(d_hl0), sym<__nv_bfloat16>(d_hl1) };
    int*   deg  = sym<int>(d_deg);
    int*   offs = sym<int>(d_offs);
    int*   cnt  = sym<int>(d_cnt);
    float* avg  = sym<float>(d_avg);
    float* S    = sym<float>(d_S);
    float* T1   = sym<float>(d_T1);
    float* uv   = sym<float>(d_uv);
    float* Yb   = sym<float>(d_Y);
    float* cbias= sym<float>(d_cbias);
    float* g    = sym<float>(d_g);
    __nv_bfloat16* Wch = sym<__nv_bfloat16>(d_Wch); __nv_bfloat16* Wcl = sym<__nv_bfloat16>(d_Wcl);
    __nv_bfloat16* Qch = sym<__nv_bfloat16>(d_Qch); __nv_bfloat16* Qcl = sym<__nv_bfloat16>(d_Qcl);

    cudaFuncSetAttribute(hmma_kernel, cudaFuncAttributeMaxDynamicSharedMemorySize, TSMEM);

    const int TPB = 256;

    // ---- graph structure ----
    cudaMemsetAsync(deg, 0, NN * sizeof(int), 0);
    cudaMemsetAsync(avg, 0, sizeof(float), 0);
    cudaMemsetAsync(cbias, 0, LL * 3 * HH * sizeof(float), 0);
    count_kernel<<<(EE + TPB - 1) / TPB, TPB>>>(dst, EE);
    scan_kernel<<<1, 1024>>>();
    cudaMemcpyAsync(cnt, offs, NN * sizeof(int), cudaMemcpyDeviceToDevice, 0);
    scatter_kernel<<<(EE + TPB - 1) / TPB, TPB>>>(src, dst, eattr, EE);
    logdeg_sum_kernel<<<256, 256>>>();
    scalers_kernel<<<(NN + TPB - 1) / TPB, TPB>>>();

    // ---- node embedding: GEMM straight into bf16 splits ----
    {
        dim3 grid(HH / 128, (NN + 127) / 128);
        sgemm_split_kernel<<<grid, 256>>>(x, FIN, nW, HH, NN, HH, FIN, nb, hh[0], hl[0]);
    }

    // ---- batched per-layer weight precompute ----
    gemm_b(eW, HH, 0, encW, HH, (long)HH * HH, T1, HH, (long)EIN * HH, EIN, HH, HH);
    gemm_b(T1, HH, (long)EIN * HH, preW + 2 * HH * HH, HH, (long)3 * HH * HH,
           S, HH, (long)EIN * HH, EIN, HH, HH);
    gemm_b(postW, HH, (long)13 * HH * HH, linW, HH, (long)HH * HH,
           Yb, HH, (long)13 * HH * HH, 13 * HH, HH, HH);
    vecmatb_kernel<<<LL, HH>>>(eb, 0, encW, HH, (long)HH * HH, encb, HH, uv, HH);
    vecmatb_kernel<<<LL, HH>>>(uv, HH, preW + 2 * HH * HH, HH, (long)3 * HH * HH,
                               preb, HH, cbias, 3 * HH);
    vecmatb_kernel<<<LL, HH>>>(postb, HH, linW, HH, (long)HH * HH,
                               linb, HH, cbias + 256, 3 * HH);
    {
        dim3 gw((384 * 128 + TPB - 1) / TPB, 1, LL);
        wconv_kernel<<<gw, TPB>>>(preW);
        dim3 gq(512 / 32, 128 / 32, LL * 3);
        qconv_kernel<<<gq, dim3(32, 8)>>>();
    }

    // ---- layers ----
    int cb = 0;
    for (int l = 0; l < LL; l++) {
        // cmb = h @ [W0 | W1 | Q0] + [tl|0|b2]  -> [hd+tl | hs | z+b2], N=384
        tgemm(hh[cb], hl[cb], Wch + (size_t)l * 3 * HH * HH, Wcl + (size_t)l * 3 * HH * HH,
              cmb, 3 * HH, NN, 3 * HH, HH, cbias + l * 3 * HH);
        // segmented aggregation with fused rank-16 edge message -> agg splits [N,512]
        agg_kernel<<<4096, 128>>>(S + (size_t)l * EIN * HH);
        // y = agg @ Qcat_l  [N,384]
        tgemm(agh, agl, Qch + (size_t)l * 384 * 512, Qcl + (size_t)l * 384 * 512,
              y, 3 * HH, NN, 3 * HH, 4 * HH, nullptr);
        // combine -> splits only
        combine_kernel<<<(NN * 32 + TPB - 1) / TPB, TPB>>>(hh[cb ^ 1], hl[cb ^ 1]);
        cb ^= 1;
    }

    // ---- pool + head ----
    cudaMemsetAsync(g, 0, GG * HH * sizeof(float), 0);
    pool_kernel<<<(NN * HH + TPB - 1) / TPB, TPB>>>(hh[cb], hl[cb], batch);
    head_kernel<<<GG, HH>>>(headW, headb, out);
}